// round 12
// baseline (speedup 1.0000x reference)
#include <cuda_runtime.h>
#include <math.h>

#define N_RESV 384
#define CSV    384
#define CZV    128
#define NHV    12
#define CHV    16
#define NQPV   4
#define NPVV   8
#define DPROJ  1152
#define DCAT   2112
#define NROWS  (N_RESV * N_RESV)
#define SPLITK 4
#define KSLICE (DCAT / SPLITK)   // 528

typedef unsigned long long ull;

__device__ __forceinline__ ull pack2(float x, float y) {
    ull r; asm("mov.b64 %0, {%1,%2};" : "=l"(r) : "f"(x), "f"(y)); return r;
}
__device__ __forceinline__ ull ffma2(ull a, ull b, ull c) {
    ull d; asm("fma.rn.f32x2 %0, %1, %2, %3;" : "=l"(d) : "l"(a), "l"(b), "l"(c)); return d;
}
__device__ __forceinline__ float2 unpack2(ull p) {
    float x, y; asm("mov.b64 {%0,%1}, %2;" : "=f"(x), "=f"(y) : "l"(p));
    return make_float2(x, y);
}
__device__ __forceinline__ unsigned smem_u32(const void* p) {
    unsigned a;
    asm("{ .reg .u64 t; cvta.to.shared.u64 t, %1; cvt.u32.u64 %0, t; }"
        : "=r"(a) : "l"(p));
    return a;
}

// ---------------- scratch ----------------------------------------------------
__device__ float g_Wcat[CSV * DPROJ];
__device__ float g_bcat[DPROJ];
__device__ float g_raw [N_RESV * DPROJ];
__device__ float g_q [NHV * N_RESV * CHV];
__device__ float g_k [NHV * N_RESV * CHV];
__device__ float g_v [NHV * N_RESV * CHV];
__device__ float g_tqp[NHV * NQPV * N_RESV * 3];
__device__ float g_tkp[NHV * NQPV * N_RESV * 3];
__device__ float g_tvp[NHV * NPVV * N_RESV * 3];
__device__ float g_bias[NHV * NROWS];
__device__ float g_concat[N_RESV * DCAT];
__device__ float g_part[SPLITK * N_RESV * N_RESV];

// ---------------- kernel 1: build concatenated projection weights ------------
__global__ void build_wcat_kernel(
    const float* Wq, const float* bq, const float* Wk, const float* bk,
    const float* Wv, const float* bv, const float* Wqp, const float* bqp,
    const float* Wkp, const float* bkp, const float* Wvp, const float* bvp)
{
    int idx = blockIdx.x * blockDim.x + threadIdx.x;
    int stride = gridDim.x * blockDim.x;
    const int total = CSV * DPROJ;
    for (int t = idx; t < total; t += stride) {
        int c = t / DPROJ, d = t % DPROJ;
        float v;
        if      (d < 192)  v = Wq [c * 192 + d];
        else if (d < 384)  v = Wk [c * 192 + (d - 192)];
        else if (d < 576)  v = Wv [c * 192 + (d - 384)];
        else if (d < 720)  v = Wqp[c * 144 + (d - 576)];
        else if (d < 864)  v = Wkp[c * 144 + (d - 720)];
        else               v = Wvp[c * 288 + (d - 864)];
        g_Wcat[t] = v;
    }
    for (int d = idx; d < DPROJ; d += stride) {
        float v;
        if      (d < 192)  v = bq [d];
        else if (d < 384)  v = bk [d - 192];
        else if (d < 576)  v = bv [d - 384];
        else if (d < 720)  v = bqp[d - 576];
        else if (d < 864)  v = bkp[d - 720];
        else               v = bvp[d - 864];
        g_bcat[d] = v;
    }
}

// ---------- GEMM 32x64 tile, 2x4 per thread, 256 threads (proj) --------------
__global__ void gemm32_kernel(const float* __restrict__ A, int lda,
                              const float* __restrict__ W, int ldw,
                              const float* __restrict__ bias,
                              float* __restrict__ C, int ldc, int K)
{
    __shared__ float sA[16][36];
    __shared__ float sB[16][68];
    int i0 = blockIdx.x * 32;
    int o0 = blockIdx.y * 64;

    int t  = threadIdx.x;
    int tc = t & 15;
    int tr = t >> 4;

    int ar = t >> 2;
    int ak = (t & 3) * 4;
    int bk = t >> 4;
    int bn = (t & 15) * 4;

    ull acc2[2][2];
    acc2[0][0] = acc2[0][1] = acc2[1][0] = acc2[1][1] = 0ull;

    for (int kk = 0; kk < K; kk += 16) {
        __syncthreads();
        if (t < 128) {
            float4 av = *(const float4*)&A[(size_t)(i0 + ar) * lda + kk + ak];
            sA[ak + 0][ar] = av.x;
            sA[ak + 1][ar] = av.y;
            sA[ak + 2][ar] = av.z;
            sA[ak + 3][ar] = av.w;
        }
        float4 bv = *(const float4*)&W[(size_t)(kk + bk) * ldw + o0 + bn];
        *(float4*)&sB[bk][bn] = bv;
        __syncthreads();
#pragma unroll
        for (int k = 0; k < 16; k++) {
            float2 a = *(const float2*)&sA[k][tr * 2];
            ulonglong2 b2 = *(const ulonglong2*)&sB[k][tc * 4];
            ull a0 = pack2(a.x, a.x);
            ull a1 = pack2(a.y, a.y);
            acc2[0][0] = ffma2(a0, b2.x, acc2[0][0]);
            acc2[0][1] = ffma2(a0, b2.y, acc2[0][1]);
            acc2[1][0] = ffma2(a1, b2.x, acc2[1][0]);
            acc2[1][1] = ffma2(a1, b2.y, acc2[1][1]);
        }
    }

    const float* bp = &bias[o0 + tc * 4];
    float4 bb4 = *(const float4*)bp;
#pragma unroll
    for (int i = 0; i < 2; i++) {
        float2 lo = unpack2(acc2[i][0]);
        float2 hi = unpack2(acc2[i][1]);
        float* crow = &C[(size_t)(i0 + tr * 2 + i) * ldc + o0 + tc * 4];
        *(float4*)crow = make_float4(lo.x + bb4.x, lo.y + bb4.y,
                                     hi.x + bb4.z, hi.y + bb4.w);
    }
}

// ---------- register-tiled GEMM: 64x64 tile, 4x4 per thread (final) ----------
__global__ void gemm64_kernel(const float* __restrict__ A, int lda,
                              const float* __restrict__ W, int ldw,
                              float* __restrict__ C, int ldc, int kLen)
{
    __shared__ float sA[16][68];
    __shared__ float sB[16][68];
    int i0 = blockIdx.x * 64;
    int o0 = blockIdx.y * 64;
    int k0 = blockIdx.z * kLen;
    C += (size_t)blockIdx.z * (size_t)(gridDim.x * 64) * ldc;

    int t  = threadIdx.x;
    int tc = t & 15;
    int tr = t >> 4;

    int ar = t >> 2;
    int ak = (t & 3) * 4;
    int bk = t >> 4;
    int bn = (t & 15) * 4;

    ull acc2[4][2];
#pragma unroll
    for (int i = 0; i < 4; i++) { acc2[i][0] = 0ull; acc2[i][1] = 0ull; }

    for (int kk = 0; kk < kLen; kk += 16) {
        __syncthreads();
        float4 av = *(const float4*)&A[(size_t)(i0 + ar) * lda + k0 + kk + ak];
        sA[ak + 0][ar] = av.x;
        sA[ak + 1][ar] = av.y;
        sA[ak + 2][ar] = av.z;
        sA[ak + 3][ar] = av.w;
        float4 bv = *(const float4*)&W[(size_t)(k0 + kk + bk) * ldw + o0 + bn];
        *(float4*)&sB[bk][bn] = bv;
        __syncthreads();
#pragma unroll
        for (int k = 0; k < 16; k++) {
            float4 a = *(const float4*)&sA[k][tr * 4];
            ulonglong2 b2 = *(const ulonglong2*)&sB[k][tc * 4];
            ull a0 = pack2(a.x, a.x);
            ull a1 = pack2(a.y, a.y);
            ull a2 = pack2(a.z, a.z);
            ull a3 = pack2(a.w, a.w);
            acc2[0][0] = ffma2(a0, b2.x, acc2[0][0]);
            acc2[0][1] = ffma2(a0, b2.y, acc2[0][1]);
            acc2[1][0] = ffma2(a1, b2.x, acc2[1][0]);
            acc2[1][1] = ffma2(a1, b2.y, acc2[1][1]);
            acc2[2][0] = ffma2(a2, b2.x, acc2[2][0]);
            acc2[2][1] = ffma2(a2, b2.y, acc2[2][1]);
            acc2[3][0] = ffma2(a3, b2.x, acc2[3][0]);
            acc2[3][1] = ffma2(a3, b2.y, acc2[3][1]);
        }
    }

#pragma unroll
    for (int i = 0; i < 4; i++) {
        float2 lo = unpack2(acc2[i][0]);
        float2 hi = unpack2(acc2[i][1]);
        float* crow = &C[(size_t)(i0 + tr * 4 + i) * ldc + o0 + tc * 4];
        *(float4*)crow = make_float4(lo.x, lo.y, hi.x, hi.y);
    }
}

// ---------------- split-K reduce + bias (float4) -----------------------------
__global__ void reduce_kernel(const float* __restrict__ bias,
                              float* __restrict__ out)
{
    int idx = blockIdx.x * blockDim.x + threadIdx.x;
    if (idx >= NROWS / 4) return;
    const float4* p = (const float4*)g_part;
    float4 a = p[idx];
    float4 b = p[idx + NROWS / 4];
    float4 c = p[idx + NROWS / 2];
    float4 d = p[idx + 3 * NROWS / 4];
    int col = (idx % (N_RESV / 4)) * 4;
    float4 bv = *(const float4*)&bias[col];
    float4 o;
    o.x = a.x + b.x + c.x + d.x + bv.x;
    o.y = a.y + b.y + c.y + d.y + bv.y;
    o.z = a.z + b.z + c.z + d.z + bv.z;
    o.w = a.w + b.w + c.w + d.w + bv.w;
    ((float4*)out)[idx] = o;
}

// ---------------- kernel 3: scatter projections + transform points -----------
__global__ void scatter_kernel(const float* __restrict__ T)
{
    int i = blockIdx.x;
    const float* raw = g_raw + (size_t)i * DPROJ;
    const float* Ti  = T + (size_t)i * 16;

    for (int t = threadIdx.x; t < 768; t += blockDim.x) {
        if (t < 576) {
            int kind = t / 192, d = t % 192;
            int h = d / 16, c = d % 16;
            float v = raw[kind * 192 + d];
            if (kind == 0) v *= 0.25f;
            float* dst = (kind == 0) ? g_q : ((kind == 1) ? g_k : g_v);
            dst[(h * N_RESV + i) * CHV + c] = v;
        } else {
            int t2 = t - 576;
            int kind, hp, P, base;
            if      (t2 < 48)  { kind = 0; hp = t2;       P = NQPV; base = 576; }
            else if (t2 < 96)  { kind = 1; hp = t2 - 48;  P = NQPV; base = 720; }
            else               { kind = 2; hp = t2 - 96;  P = NPVV; base = 864; }
            int HP = NHV * P;
            float px = raw[base + 0 * HP + hp];
            float py = raw[base + 1 * HP + hp];
            float pz = raw[base + 2 * HP + hp];
            float ox = Ti[0] * px + Ti[1] * py + Ti[2]  * pz + Ti[3];
            float oy = Ti[4] * px + Ti[5] * py + Ti[6]  * pz + Ti[7];
            float oz = Ti[8] * px + Ti[9] * py + Ti[10] * pz + Ti[11];
            float* dst = (kind == 0) ? g_tqp : ((kind == 1) ? g_tkp : g_tvp);
            float* o = dst + ((size_t)hp * N_RESV + i) * 3;
            o[0] = ox; o[1] = oy; o[2] = oz;
        }
    }
}

// ---------------- kernel 4: bias = z @ Wb + bb (cp.async double-buffer) ------
__global__ void __launch_bounds__(128) bias_gemm_kernel(
    const float* __restrict__ z,
    const float* __restrict__ Wb,
    const float* __restrict__ bb)
{
    __shared__ float2 sz[2][128 * 17];
    __shared__ ull    swp[NHV * 64];
    int t = threadIdx.x;
    int r0 = blockIdx.x * 128;

    unsigned sbase0 = smem_u32(&sz[0][0]);
    unsigned sbase1 = smem_u32(&sz[1][0]);

    for (int idx = t; idx < NHV * 64; idx += 128) {
        int h = idx >> 6, q = idx & 63;
        swp[idx] = pack2(Wb[(2 * q) * NHV + h], Wb[(2 * q + 1) * NHV + h]);
    }

#pragma unroll
    for (int c0 = 0; c0 < 2; c0++) {
        unsigned sb = c0 ? sbase1 : sbase0;
        int ct = c0 * 32;
#pragma unroll
        for (int k = 0; k < 16; k++) {
            int idx = t + (k << 7);
            int row = idx >> 4, q = idx & 15;
            unsigned sa = sb + row * 136 + q * 8;
            const float* g = &z[(size_t)(r0 + row) * CZV + ct + q * 2];
            asm volatile("cp.async.ca.shared.global [%0], [%1], 8;\n"
                         :: "r"(sa), "l"(g));
        }
        asm volatile("cp.async.commit_group;\n");
    }

    ull acc[NHV];
#pragma unroll
    for (int h = 0; h < NHV; h++) acc[h] = 0ull;

#pragma unroll
    for (int c = 0; c < 4; c++) {
        if (c < 3) asm volatile("cp.async.wait_group 1;\n" ::: "memory");
        else       asm volatile("cp.async.wait_group 0;\n" ::: "memory");
        __syncthreads();
        const float2* zrow = &sz[c & 1][t * 17];
        int cbase = c << 4;
#pragma unroll
        for (int q = 0; q < 16; q++) {
            ull zp = *reinterpret_cast<const ull*>(&zrow[q]);
#pragma unroll
            for (int h = 0; h < NHV; h++)
                acc[h] = ffma2(zp, swp[(h << 6) + cbase + q], acc[h]);
        }
        if (c < 2) {
            __syncthreads();
            unsigned sb = (c & 1) ? sbase1 : sbase0;
            int ct = (c + 2) * 32;
#pragma unroll
            for (int k = 0; k < 16; k++) {
                int idx = t + (k << 7);
                int row = idx >> 4, q = idx & 15;
                unsigned sa = sb + row * 136 + q * 8;
                const float* g = &z[(size_t)(r0 + row) * CZV + ct + q * 2];
                asm volatile("cp.async.ca.shared.global [%0], [%1], 8;\n"
                             :: "r"(sa), "l"(g));
            }
            asm volatile("cp.async.commit_group;\n");
        }
    }

    int row = r0 + t;
#pragma unroll
    for (int h = 0; h < NHV; h++) {
        float2 v = unpack2(acc[h]);
        g_bias[(size_t)h * NROWS + row] = v.x + v.y + bb[h];
    }
}

// ---------------- kernel 5: FUSED attention + outputs, block per residue -----
// 384 threads: logits (thread j, all 12 heads) -> warp-per-head softmax in smem
// -> pairwise (z direct) + v_out/v_att + inverse transform, all from smem att.
__global__ void __launch_bounds__(384) fused_att_kernel(
    const float* __restrict__ z,
    const float* __restrict__ T,
    const float* __restrict__ hwt)
{
    int i = blockIdx.x;
    __shared__ float slog[NHV][N_RESV];   // 18 KB: logits -> att
    __shared__ float sq  [NHV][16];
    __shared__ float sqp [NHV][12];
    __shared__ float scoef[NHV];
    __shared__ float svatt[NHV * 24];

    int t = threadIdx.x;

    if (t < 192) {
        int h = t >> 4, c = t & 15;
        sq[h][c] = g_q[(h * N_RESV + i) * CHV + c];
    } else if (t < 336) {
        int u2 = t - 192, h = u2 / 12, u = u2 % 12, p = u / 3, d = u % 3;
        sqp[h][u] = g_tqp[((h * NQPV + p) * N_RESV + i) * 3 + d];
    } else if (t < 348) {
        int h = t - 336;
        float hw = hwt[h];
        float gamma = (hw > 20.f) ? hw : log1pf(expf(hw));
        scoef[h] = gamma * 0.23570226039551584f * 0.5f;
    }
    __syncthreads();

    const float wl = 0.57735026918962576f;

    // ---- logits: thread j = t computes all 12 heads ----
    {
        int j = t;
#pragma unroll 3
        for (int h = 0; h < NHV; h++) {
            const float4* kr = (const float4*)&g_k[(h * N_RESV + j) * CHV];
            float4 k0 = kr[0], k1 = kr[1], k2 = kr[2], k3 = kr[3];
            float qk = sq[h][0]  * k0.x + sq[h][1]  * k0.y
                     + sq[h][2]  * k0.z + sq[h][3]  * k0.w
                     + sq[h][4]  * k1.x + sq[h][5]  * k1.y
                     + sq[h][6]  * k1.z + sq[h][7]  * k1.w
                     + sq[h][8]  * k2.x + sq[h][9]  * k2.y
                     + sq[h][10] * k2.z + sq[h][11] * k2.w
                     + sq[h][12] * k3.x + sq[h][13] * k3.y
                     + sq[h][14] * k3.z + sq[h][15] * k3.w;
            float d2 = 0.f;
#pragma unroll
            for (int p = 0; p < NQPV; p++) {
                const float* kp = &g_tkp[((h * NQPV + p) * N_RESV + j) * 3];
                float dx = sqp[h][p * 3 + 0] - kp[0];
                float dy = sqp[h][p * 3 + 1] - kp[1];
                float dz = sqp[h][p * 3 + 2] - kp[2];
                d2 += dx * dx + dy * dy + dz * dz;
            }
            float b = g_bias[(size_t)h * NROWS + (size_t)i * N_RESV + j];
            slog[h][j] = wl * (qk + b - scoef[h] * d2);
        }
    }
    __syncthreads();

    // ---- softmax: warp w handles head w ----
    {
        int w = t >> 5, lane = t & 31;
        float m = -1e30f;
#pragma unroll
        for (int r = 0; r < 12; r++) m = fmaxf(m, slog[w][lane + r * 32]);
#pragma unroll
        for (int o = 16; o; o >>= 1) m = fmaxf(m, __shfl_xor_sync(0xffffffffu, m, o));
        float ss = 0.f;
#pragma unroll
        for (int r = 0; r < 12; r++) {
            float e = expf(slog[w][lane + r * 32] - m);
            slog[w][lane + r * 32] = e;
            ss += e;
        }
#pragma unroll
        for (int o = 16; o; o >>= 1) ss += __shfl_xor_sync(0xffffffffu, ss, o);
        float inv = 1.f / ss;
#pragma unroll
        for (int r = 0; r < 12; r++) slog[w][lane + r * 32] *= inv;
    }
    __syncthreads();

    float* crow = g_concat + (size_t)i * DCAT;

    // ---- pairwise: h = t>>5, c-quad = t&31, z direct from L2 ----
    {
        int h = t >> 5, c4 = t & 31;
        const ulonglong2* zbase = (const ulonglong2*)(z + (size_t)i * N_RESV * CZV) + c4;
        const float* arow = slog[h];
        ull a01 = 0ull, a23 = 0ull;
#pragma unroll 4
        for (int j = 0; j < N_RESV; j++) {
            float a = arow[j];
            ull ap = pack2(a, a);
            ulonglong2 zp = __ldg(zbase + (size_t)j * 32);
            a01 = ffma2(ap, zp.x, a01);
            a23 = ffma2(ap, zp.y, a23);
        }
        float2 lo = unpack2(a01), hi = unpack2(a23);
        *(float4*)&crow[576 + h * CZV + c4 * 4] = make_float4(lo.x, lo.y, hi.x, hi.y);
    }

    // ---- v_out / v_att: 480 tasks over 384 threads ----
    {
        float accA = 0.f;
        int hA, colA, strideA;
        const float* xA;
        if (t < 192) {
            hA = t >> 4; colA = t & 15; strideA = CHV;
            xA = &g_v[(size_t)(hA * N_RESV) * CHV + colA];
        } else {
            int u = t - 192;
            hA = u / 24; int r = u % 24, p = r / 3, d = r % 3;
            strideA = 3; colA = 0;
            xA = &g_tvp[((size_t)(hA * NPVV + p) * N_RESV) * 3 + d];
        }
        const float* arowA = slog[hA];
#pragma unroll 4
        for (int j = 0; j < N_RESV; j++)
            accA = fmaf(arowA[j], __ldg(&xA[(size_t)j * strideA]), accA);

        float accB = 0.f;
        if (t < 96) {
            int u = t + 192;
            int hB = u / 24; int r = u % 24, p = r / 3, d = r % 3;
            const float* xB = &g_tvp[((size_t)(hB * NPVV + p) * N_RESV) * 3 + d];
            const float* arowB = slog[hB];
#pragma unroll 4
            for (int j = 0; j < N_RESV; j++)
                accB = fmaf(arowB[j], __ldg(&xB[(size_t)j * 3]), accB);
        }

        if (t < 192) crow[hA * CHV + colA] = accA;
        else         svatt[t - 192] = accA;
        if (t < 96)  svatt[192 + t] = accB;
    }
    __syncthreads();

    // ---- inverse transform + norm ----
    const float* Ti = T + (size_t)i * 16;
    if (t < 96) {
        int hh = t / 8, p = t % 8;
        const float* av = &svatt[hh * 24 + p * 3];
        float px = av[0] - Ti[3];
        float py = av[1] - Ti[7];
        float pz = av[2] - Ti[11];
        float ox = Ti[0] * px + Ti[4] * py + Ti[8]  * pz;
        float oy = Ti[1] * px + Ti[5] * py + Ti[9]  * pz;
        float oz = Ti[2] * px + Ti[6] * py + Ti[10] * pz;
        crow[192 +   0 + hh * 8 + p] = ox;
        crow[192 +  96 + hh * 8 + p] = oy;
        crow[192 + 192 + hh * 8 + p] = oz;
        crow[480 + hh * 8 + p] = sqrtf(ox * ox + oy * oy + oz * oz);
    }
}

// ---------------- launch ------------------------------------------------------
extern "C" void kernel_launch(void* const* d_in, const int* in_sizes, int n_in,
                              void* d_out, int out_size)
{
    const float* s   = (const float*)d_in[0];
    const float* z   = (const float*)d_in[1];
    const float* T   = (const float*)d_in[2];
    const float* Wq  = (const float*)d_in[3];
    const float* bq  = (const float*)d_in[4];
    const float* Wk  = (const float*)d_in[5];
    const float* bk  = (const float*)d_in[6];
    const float* Wv  = (const float*)d_in[7];
    const float* bv  = (const float*)d_in[8];
    const float* Wqp = (const float*)d_in[9];
    const float* bqp = (const float*)d_in[10];
    const float* Wkp = (const float*)d_in[11];
    const float* bkp = (const float*)d_in[12];
    const float* Wvp = (const float*)d_in[13];
    const float* bvp = (const float*)d_in[14];
    const float* Wb  = (const float*)d_in[15];
    const float* bb  = (const float*)d_in[16];
    const float* Wo  = (const float*)d_in[17];
    const float* bo  = (const float*)d_in[18];
    const float* hwt = (const float*)d_in[19];

    float* out = (float*)d_out;

    float* raw_p;    cudaGetSymbolAddress((void**)&raw_p,    g_raw);
    float* wcat_p;   cudaGetSymbolAddress((void**)&wcat_p,   g_Wcat);
    float* bcat_p;   cudaGetSymbolAddress((void**)&bcat_p,   g_bcat);
    float* concat_p; cudaGetSymbolAddress((void**)&concat_p, g_concat);
    float* part_p;   cudaGetSymbolAddress((void**)&part_p,   g_part);

    build_wcat_kernel<<<432, 256>>>(Wq, bq, Wk, bk, Wv, bv,
                                    Wqp, bqp, Wkp, bkp, Wvp, bvp);

    gemm32_kernel<<<dim3(N_RESV / 32, DPROJ / 64), 256>>>(
        s, CSV, wcat_p, DPROJ, bcat_p, raw_p, DPROJ, CSV);

    scatter_kernel<<<N_RESV, 256>>>(T);

    bias_gemm_kernel<<<NROWS / 128, 128>>>(z, Wb, bb);

    fused_att_kernel<<<N_RESV, 384>>>(z, T, hwt);

    gemm64_kernel<<<dim3(N_RESV / 64, N_RESV / 64, SPLITK), 256>>>(
        concat_p, DCAT, Wo, CSV, part_p, CSV, KSLICE);

    reduce_kernel<<<(NROWS / 4 + 255) / 256, 256>>>(bo, out);
}

// round 13
// speedup vs baseline: 1.1707x; 1.1707x over previous
#include <cuda_runtime.h>
#include <math.h>

#define N_RESV 384
#define CSV    384
#define CZV    128
#define NHV    12
#define CHV    16
#define NQPV   4
#define NPVV   8
#define DPROJ  1152
#define DCAT   2112
#define NROWS  (N_RESV * N_RESV)
#define SPLITK 4
#define KSLICE (DCAT / SPLITK)   // 528

typedef unsigned long long ull;

__device__ __forceinline__ ull pack2(float x, float y) {
    ull r; asm("mov.b64 %0, {%1,%2};" : "=l"(r) : "f"(x), "f"(y)); return r;
}
__device__ __forceinline__ ull ffma2(ull a, ull b, ull c) {
    ull d; asm("fma.rn.f32x2 %0, %1, %2, %3;" : "=l"(d) : "l"(a), "l"(b), "l"(c)); return d;
}
__device__ __forceinline__ float2 unpack2(ull p) {
    float x, y; asm("mov.b64 {%0,%1}, %2;" : "=f"(x), "=f"(y) : "l"(p));
    return make_float2(x, y);
}
__device__ __forceinline__ unsigned smem_u32(const void* p) {
    unsigned a;
    asm("{ .reg .u64 t; cvta.to.shared.u64 t, %1; cvt.u32.u64 %0, t; }"
        : "=r"(a) : "l"(p));
    return a;
}

// ---------------- scratch ----------------------------------------------------
__device__ float g_raw [N_RESV * DPROJ];
__device__ float g_q [NHV * N_RESV * CHV];
__device__ float g_k [NHV * N_RESV * CHV];
__device__ float g_v [NHV * N_RESV * CHV];
__device__ float g_tqp[NHV * NQPV * N_RESV * 3];
__device__ float g_tkp[NHV * NQPV * N_RESV * 3];
__device__ float g_tvp[NHV * NPVV * N_RESV * 3];
__device__ float g_bias[NHV * NROWS];
__device__ float g_att [NHV * NROWS];
__device__ float g_av  [NHV * N_RESV * 40];
__device__ float g_concat[N_RESV * DCAT];
__device__ float g_part[SPLITK * N_RESV * N_RESV];

// ---------- projection GEMM reading raw weight matrices directly -------------
// 32x64 tile, 2x4 per thread, 256 threads. Region per thread resolved once.
__global__ void proj_gemm_kernel(
    const float* __restrict__ s,
    const float* Wq, const float* bq, const float* Wk, const float* bk,
    const float* Wv, const float* bv, const float* Wqp, const float* bqp,
    const float* Wkp, const float* bkp, const float* Wvp, const float* bvp)
{
    __shared__ float sA[16][36];
    __shared__ float sB[16][68];
    int i0 = blockIdx.x * 32;
    int o0 = blockIdx.y * 64;

    int t  = threadIdx.x;
    int tc = t & 15;
    int tr = t >> 4;

    int ar = t >> 2;
    int ak = (t & 3) * 4;
    int bk2 = t >> 4;
    int bn = (t & 15) * 4;

    // resolve B-load source for columns d..d+3 (never cross region boundary)
    int d = o0 + bn;
    const float* wsrc; const float* bsrc; int ldwS, colS;
    if      (d < 192)  { wsrc = Wq;  bsrc = bq;  ldwS = 192; colS = d; }
    else if (d < 384)  { wsrc = Wk;  bsrc = bk;  ldwS = 192; colS = d - 192; }
    else if (d < 576)  { wsrc = Wv;  bsrc = bv;  ldwS = 192; colS = d - 384; }
    else if (d < 720)  { wsrc = Wqp; bsrc = bqp; ldwS = 144; colS = d - 576; }
    else if (d < 864)  { wsrc = Wkp; bsrc = bkp; ldwS = 144; colS = d - 720; }
    else               { wsrc = Wvp; bsrc = bvp; ldwS = 288; colS = d - 864; }

    ull acc2[2][2];
    acc2[0][0] = acc2[0][1] = acc2[1][0] = acc2[1][1] = 0ull;

    for (int kk = 0; kk < CSV; kk += 16) {
        __syncthreads();
        if (t < 128) {
            float4 av = *(const float4*)&s[(size_t)(i0 + ar) * CSV + kk + ak];
            sA[ak + 0][ar] = av.x;
            sA[ak + 1][ar] = av.y;
            sA[ak + 2][ar] = av.z;
            sA[ak + 3][ar] = av.w;
        }
        float4 bv4 = *(const float4*)&wsrc[(size_t)(kk + bk2) * ldwS + colS];
        *(float4*)&sB[bk2][bn] = bv4;
        __syncthreads();
#pragma unroll
        for (int k = 0; k < 16; k++) {
            float2 a = *(const float2*)&sA[k][tr * 2];
            ulonglong2 b2 = *(const ulonglong2*)&sB[k][tc * 4];
            ull a0 = pack2(a.x, a.x);
            ull a1 = pack2(a.y, a.y);
            acc2[0][0] = ffma2(a0, b2.x, acc2[0][0]);
            acc2[0][1] = ffma2(a0, b2.y, acc2[0][1]);
            acc2[1][0] = ffma2(a1, b2.x, acc2[1][0]);
            acc2[1][1] = ffma2(a1, b2.y, acc2[1][1]);
        }
    }

    float4 bb4 = *(const float4*)&bsrc[colS];
#pragma unroll
    for (int i = 0; i < 2; i++) {
        float2 lo = unpack2(acc2[i][0]);
        float2 hi = unpack2(acc2[i][1]);
        float* crow = &g_raw[(size_t)(i0 + tr * 2 + i) * DPROJ + o0 + tc * 4];
        *(float4*)crow = make_float4(lo.x + bb4.x, lo.y + bb4.y,
                                     hi.x + bb4.z, hi.y + bb4.w);
    }
}

// ---------- register-tiled GEMM: 64x64 tile, 4x4 per thread (final) ----------
__global__ void gemm64_kernel(const float* __restrict__ A, int lda,
                              const float* __restrict__ W, int ldw,
                              float* __restrict__ C, int ldc, int kLen)
{
    __shared__ float sA[16][68];
    __shared__ float sB[16][68];
    int i0 = blockIdx.x * 64;
    int o0 = blockIdx.y * 64;
    int k0 = blockIdx.z * kLen;
    C += (size_t)blockIdx.z * (size_t)(gridDim.x * 64) * ldc;

    int t  = threadIdx.x;
    int tc = t & 15;
    int tr = t >> 4;

    int ar = t >> 2;
    int ak = (t & 3) * 4;
    int bk = t >> 4;
    int bn = (t & 15) * 4;

    ull acc2[4][2];
#pragma unroll
    for (int i = 0; i < 4; i++) { acc2[i][0] = 0ull; acc2[i][1] = 0ull; }

    for (int kk = 0; kk < kLen; kk += 16) {
        __syncthreads();
        float4 av = *(const float4*)&A[(size_t)(i0 + ar) * lda + k0 + kk + ak];
        sA[ak + 0][ar] = av.x;
        sA[ak + 1][ar] = av.y;
        sA[ak + 2][ar] = av.z;
        sA[ak + 3][ar] = av.w;
        float4 bv = *(const float4*)&W[(size_t)(k0 + kk + bk) * ldw + o0 + bn];
        *(float4*)&sB[bk][bn] = bv;
        __syncthreads();
#pragma unroll
        for (int k = 0; k < 16; k++) {
            float4 a = *(const float4*)&sA[k][tr * 4];
            ulonglong2 b2 = *(const ulonglong2*)&sB[k][tc * 4];
            ull a0 = pack2(a.x, a.x);
            ull a1 = pack2(a.y, a.y);
            ull a2 = pack2(a.z, a.z);
            ull a3 = pack2(a.w, a.w);
            acc2[0][0] = ffma2(a0, b2.x, acc2[0][0]);
            acc2[0][1] = ffma2(a0, b2.y, acc2[0][1]);
            acc2[1][0] = ffma2(a1, b2.x, acc2[1][0]);
            acc2[1][1] = ffma2(a1, b2.y, acc2[1][1]);
            acc2[2][0] = ffma2(a2, b2.x, acc2[2][0]);
            acc2[2][1] = ffma2(a2, b2.y, acc2[2][1]);
            acc2[3][0] = ffma2(a3, b2.x, acc2[3][0]);
            acc2[3][1] = ffma2(a3, b2.y, acc2[3][1]);
        }
    }

#pragma unroll
    for (int i = 0; i < 4; i++) {
        float2 lo = unpack2(acc2[i][0]);
        float2 hi = unpack2(acc2[i][1]);
        float* crow = &C[(size_t)(i0 + tr * 4 + i) * ldc + o0 + tc * 4];
        *(float4*)crow = make_float4(lo.x, lo.y, hi.x, hi.y);
    }
}

// ---------------- split-K reduce + bias (float4) -----------------------------
__global__ void reduce_kernel(const float* __restrict__ bias,
                              float* __restrict__ out)
{
    int idx = blockIdx.x * blockDim.x + threadIdx.x;
    if (idx >= NROWS / 4) return;
    const float4* p = (const float4*)g_part;
    float4 a = p[idx];
    float4 b = p[idx + NROWS / 4];
    float4 c = p[idx + NROWS / 2];
    float4 d = p[idx + 3 * NROWS / 4];
    int col = (idx % (N_RESV / 4)) * 4;
    float4 bv = *(const float4*)&bias[col];
    float4 o;
    o.x = a.x + b.x + c.x + d.x + bv.x;
    o.y = a.y + b.y + c.y + d.y + bv.y;
    o.z = a.z + b.z + c.z + d.z + bv.z;
    o.w = a.w + b.w + c.w + d.w + bv.w;
    ((float4*)out)[idx] = o;
}

// ---------------- kernel 3: scatter projections + transform points -----------
__global__ void scatter_kernel(const float* __restrict__ T)
{
    int i = blockIdx.x;
    const float* raw = g_raw + (size_t)i * DPROJ;
    const float* Ti  = T + (size_t)i * 16;

    for (int t = threadIdx.x; t < 768; t += blockDim.x) {
        if (t < 576) {
            int kind = t / 192, d = t % 192;
            int h = d / 16, c = d % 16;
            float v = raw[kind * 192 + d];
            if (kind == 0) v *= 0.25f;
            float* dst = (kind == 0) ? g_q : ((kind == 1) ? g_k : g_v);
            dst[(h * N_RESV + i) * CHV + c] = v;
        } else {
            int t2 = t - 576;
            int kind, hp, P, base;
            if      (t2 < 48)  { kind = 0; hp = t2;       P = NQPV; base = 576; }
            else if (t2 < 96)  { kind = 1; hp = t2 - 48;  P = NQPV; base = 720; }
            else               { kind = 2; hp = t2 - 96;  P = NPVV; base = 864; }
            int HP = NHV * P;
            float px = raw[base + 0 * HP + hp];
            float py = raw[base + 1 * HP + hp];
            float pz = raw[base + 2 * HP + hp];
            float ox = Ti[0] * px + Ti[1] * py + Ti[2]  * pz + Ti[3];
            float oy = Ti[4] * px + Ti[5] * py + Ti[6]  * pz + Ti[7];
            float oz = Ti[8] * px + Ti[9] * py + Ti[10] * pz + Ti[11];
            float* dst = (kind == 0) ? g_tqp : ((kind == 1) ? g_tkp : g_tvp);
            float* o = dst + ((size_t)hp * N_RESV + i) * 3;
            o[0] = ox; o[1] = oy; o[2] = oz;
        }
    }
}

// ---------------- kernel 4: bias = z @ Wb + bb (cp.async double-buffer) ------
__global__ void __launch_bounds__(128) bias_gemm_kernel(
    const float* __restrict__ z,
    const float* __restrict__ Wb,
    const float* __restrict__ bb)
{
    __shared__ float2 sz[2][128 * 17];
    __shared__ ull    swp[NHV * 64];
    int t = threadIdx.x;
    int r0 = blockIdx.x * 128;

    unsigned sbase0 = smem_u32(&sz[0][0]);
    unsigned sbase1 = smem_u32(&sz[1][0]);

    for (int idx = t; idx < NHV * 64; idx += 128) {
        int h = idx >> 6, q = idx & 63;
        swp[idx] = pack2(Wb[(2 * q) * NHV + h], Wb[(2 * q + 1) * NHV + h]);
    }

#pragma unroll
    for (int c0 = 0; c0 < 2; c0++) {
        unsigned sb = c0 ? sbase1 : sbase0;
        int ct = c0 * 32;
#pragma unroll
        for (int k = 0; k < 16; k++) {
            int idx = t + (k << 7);
            int row = idx >> 4, q = idx & 15;
            unsigned sa = sb + row * 136 + q * 8;
            const float* g = &z[(size_t)(r0 + row) * CZV + ct + q * 2];
            asm volatile("cp.async.ca.shared.global [%0], [%1], 8;\n"
                         :: "r"(sa), "l"(g));
        }
        asm volatile("cp.async.commit_group;\n");
    }

    ull acc[NHV];
#pragma unroll
    for (int h = 0; h < NHV; h++) acc[h] = 0ull;

#pragma unroll
    for (int c = 0; c < 4; c++) {
        if (c < 3) asm volatile("cp.async.wait_group 1;\n" ::: "memory");
        else       asm volatile("cp.async.wait_group 0;\n" ::: "memory");
        __syncthreads();
        const float2* zrow = &sz[c & 1][t * 17];
        int cbase = c << 4;
#pragma unroll
        for (int q = 0; q < 16; q++) {
            ull zp = *reinterpret_cast<const ull*>(&zrow[q]);
#pragma unroll
            for (int h = 0; h < NHV; h++)
                acc[h] = ffma2(zp, swp[(h << 6) + cbase + q], acc[h]);
        }
        if (c < 2) {
            __syncthreads();
            unsigned sb = (c & 1) ? sbase1 : sbase0;
            int ct = (c + 2) * 32;
#pragma unroll
            for (int k = 0; k < 16; k++) {
                int idx = t + (k << 7);
                int row = idx >> 4, q = idx & 15;
                unsigned sa = sb + row * 136 + q * 8;
                const float* g = &z[(size_t)(r0 + row) * CZV + ct + q * 2];
                asm volatile("cp.async.ca.shared.global [%0], [%1], 8;\n"
                             :: "r"(sa), "l"(g));
            }
            asm volatile("cp.async.commit_group;\n");
        }
    }

    int row = r0 + t;
#pragma unroll
    for (int h = 0; h < NHV; h++) {
        float2 v = unpack2(acc[h]);
        g_bias[(size_t)h * NROWS + row] = v.x + v.y + bb[h];
    }
}

// ---------------- kernel 5: logits + softmax. grid (48, 12), block 256 -------
__global__ void att_kernel(const float* __restrict__ head_weights)
{
    int h = blockIdx.y;
    int i0 = blockIdx.x * 8;
    __shared__ float sk [32][17];
    __shared__ float skp[32][12];
    __shared__ float sq [8][16];
    __shared__ float sqp[8][12];
    __shared__ float slog[8][N_RESV];

    int t = threadIdx.x, w = t >> 5, lane = t & 31;

    if (t < 128) {
        int iw = t / 16, c = t % 16;
        sq[iw][c] = g_q[(h * N_RESV + i0 + iw) * CHV + c];
    }
    if (t < 96) {
        int iw = t / 12, u = t % 12, p = u / 3, d = u % 3;
        sqp[iw][u] = g_tqp[((h * NQPV + p) * N_RESV + i0 + iw) * 3 + d];
    }
    float hw = head_weights[h];
    float gamma = (hw > 20.f) ? hw : log1pf(expf(hw));
    const float wc = 0.23570226039551584f;
    const float wl = 0.57735026918962576f;
    float coef = gamma * wc * 0.5f;

    const float* brow = &g_bias[(size_t)h * NROWS + (size_t)(i0 + w) * N_RESV];

    for (int j0 = 0; j0 < N_RESV; j0 += 32) {
        __syncthreads();
        for (int idx = t; idx < 32 * 16; idx += 256)
            sk[idx >> 4][idx & 15] = g_k[(h * N_RESV + j0 + (idx >> 4)) * CHV + (idx & 15)];
        for (int idx = t; idx < 32 * 12; idx += 256) {
            int j = idx / 12, u = idx % 12, p = u / 3, d = u % 3;
            skp[j][u] = g_tkp[((h * NQPV + p) * N_RESV + j0 + j) * 3 + d];
        }
        __syncthreads();
        int j = j0 + lane;
        float qk = 0.f;
#pragma unroll
        for (int c = 0; c < CHV; c++) qk = fmaf(sq[w][c], sk[lane][c], qk);
        float d2 = 0.f;
#pragma unroll
        for (int p = 0; p < NQPV; p++) {
            float dx = sqp[w][p * 3 + 0] - skp[lane][p * 3 + 0];
            float dy = sqp[w][p * 3 + 1] - skp[lane][p * 3 + 1];
            float dz = sqp[w][p * 3 + 2] - skp[lane][p * 3 + 2];
            d2 += dx * dx + dy * dy + dz * dz;
        }
        slog[w][j] = wl * (qk + brow[j] - coef * d2);
    }

    float m = -1e30f;
#pragma unroll
    for (int r = 0; r < 12; r++) m = fmaxf(m, slog[w][lane + r * 32]);
#pragma unroll
    for (int o = 16; o; o >>= 1) m = fmaxf(m, __shfl_xor_sync(0xffffffffu, m, o));
    float ssum = 0.f;
#pragma unroll
    for (int r = 0; r < 12; r++) {
        float e = expf(slog[w][lane + r * 32] - m);
        slog[w][lane + r * 32] = e;
        ssum += e;
    }
#pragma unroll
    for (int o = 16; o; o >>= 1) ssum += __shfl_xor_sync(0xffffffffu, ssum, o);
    float inv = 1.f / ssum;
    float* arow = &g_att[(size_t)h * NROWS + (size_t)(i0 + w) * N_RESV];
#pragma unroll
    for (int r = 0; r < 12; r++) arow[lane + r * 32] = slog[w][lane + r * 32] * inv;
}

// ---------------- kernel 6: per-head GEMM  att[h] @ [v|vp], f32x2 ------------
__global__ void att_av_kernel()
{
    int h = blockIdx.y;
    int i0 = blockIdx.x * 32;
    __shared__ float satt[32][65];
    __shared__ float sx[64][44];
    int t = threadIdx.x;
    int r  = t / 10;
    int c0 = (t % 10) * 4;
    ull acc2[2];
    acc2[0] = 0ull; acc2[1] = 0ull;

    for (int j0 = 0; j0 < N_RESV; j0 += 64) {
        __syncthreads();
        for (int idx = t; idx < 32 * 16; idx += 320) {
            int row = idx >> 4, v4 = idx & 15;
            float4 v = *(const float4*)&g_att[((size_t)h * N_RESV + i0 + row) * N_RESV + j0 + v4 * 4];
            float* dst = &satt[row][v4 * 4];
            dst[0] = v.x; dst[1] = v.y; dst[2] = v.z; dst[3] = v.w;
        }
        for (int idx = t; idx < 64 * 40; idx += 320) {
            int j = idx / 40, col = idx % 40;
            float v;
            if (col < 16) v = g_v[(h * N_RESV + j0 + j) * CHV + col];
            else {
                int u = col - 16, p = u / 3, d = u % 3;
                v = g_tvp[((h * NPVV + p) * N_RESV + j0 + j) * 3 + d];
            }
            sx[j][col] = v;
        }
        __syncthreads();
#pragma unroll 4
        for (int jj = 0; jj < 64; jj++) {
            float a = satt[r][jj];
            ull ap = pack2(a, a);
            ulonglong2 xr = *(const ulonglong2*)&sx[jj][c0];
            acc2[0] = ffma2(ap, xr.x, acc2[0]);
            acc2[1] = ffma2(ap, xr.y, acc2[1]);
        }
    }
    float2 lo = unpack2(acc2[0]);
    float2 hi = unpack2(acc2[1]);
    float* orow = &g_av[((size_t)h * N_RESV + i0 + r) * 40 + c0];
    *(float4*)orow = make_float4(lo.x, lo.y, hi.x, hi.y);
}

// ---------------- kernel 7: pairwise GEMM + finalize (direct-LDG, f32x2) -----
__global__ void out_kernel(const float* __restrict__ z,
                           const float* __restrict__ T)
{
    int i = blockIdx.x;
    __shared__ float att[NHV][N_RESV];
    int t = threadIdx.x;

    for (int idx = t; idx < NHV * N_RESV / 4; idx += 384) {
        int h = idx / (N_RESV / 4), q = idx % (N_RESV / 4);
        float4 v = *(const float4*)&g_att[((size_t)h * N_RESV + i) * N_RESV + q * 4];
        *(float4*)&att[h][q * 4] = v;
    }
    __syncthreads();

    int h  = t >> 5;
    int c4 = t & 31;
    const ulonglong2* zbase = (const ulonglong2*)(z + (size_t)i * N_RESV * CZV) + c4;
    const float* arow = att[h];

    ull acc01 = 0ull, acc23 = 0ull;
#pragma unroll 4
    for (int j = 0; j < N_RESV; j++) {
        float a = arow[j];
        ull ap = pack2(a, a);
        ulonglong2 zp = __ldg(zbase + (size_t)j * 32);
        acc01 = ffma2(ap, zp.x, acc01);
        acc23 = ffma2(ap, zp.y, acc23);
    }
    float2 lo = unpack2(acc01);
    float2 hi = unpack2(acc23);
    float* crow = g_concat + (size_t)i * DCAT;
    *(float4*)&crow[576 + h * CZV + c4 * 4] = make_float4(lo.x, lo.y, hi.x, hi.y);

    if (t < 192) {
        int hh = t / 16, cc = t % 16;
        crow[hh * 16 + cc] = g_av[((size_t)hh * N_RESV + i) * 40 + cc];
    }
    const float* Ti = T + (size_t)i * 16;
    if (t < 96) {
        int hh = t / 8, p = t % 8;
        const float* av = &g_av[((size_t)hh * N_RESV + i) * 40 + 16 + p * 3];
        float px = av[0] - Ti[3];
        float py = av[1] - Ti[7];
        float pz = av[2] - Ti[11];
        float ox = Ti[0] * px + Ti[4] * py + Ti[8]  * pz;
        float oy = Ti[1] * px + Ti[5] * py + Ti[9]  * pz;
        float oz = Ti[2] * px + Ti[6] * py + Ti[10] * pz;
        crow[192 +   0 + hh * 8 + p] = ox;
        crow[192 +  96 + hh * 8 + p] = oy;
        crow[192 + 192 + hh * 8 + p] = oz;
        crow[480 + hh * 8 + p] = sqrtf(ox * ox + oy * oy + oz * oz);
    }
}

// ---------------- launch ------------------------------------------------------
extern "C" void kernel_launch(void* const* d_in, const int* in_sizes, int n_in,
                              void* d_out, int out_size)
{
    const float* s   = (const float*)d_in[0];
    const float* z   = (const float*)d_in[1];
    const float* T   = (const float*)d_in[2];
    const float* Wq  = (const float*)d_in[3];
    const float* bq  = (const float*)d_in[4];
    const float* Wk  = (const float*)d_in[5];
    const float* bk  = (const float*)d_in[6];
    const float* Wv  = (const float*)d_in[7];
    const float* bv  = (const float*)d_in[8];
    const float* Wqp = (const float*)d_in[9];
    const float* bqp = (const float*)d_in[10];
    const float* Wkp = (const float*)d_in[11];
    const float* bkp = (const float*)d_in[12];
    const float* Wvp = (const float*)d_in[13];
    const float* bvp = (const float*)d_in[14];
    const float* Wb  = (const float*)d_in[15];
    const float* bb  = (const float*)d_in[16];
    const float* Wo  = (const float*)d_in[17];
    const float* bo  = (const float*)d_in[18];
    const float* hwt = (const float*)d_in[19];

    float* out = (float*)d_out;

    float* concat_p; cudaGetSymbolAddress((void**)&concat_p, g_concat);
    float* part_p;   cudaGetSymbolAddress((void**)&part_p,   g_part);

    proj_gemm_kernel<<<dim3(N_RESV / 32, DPROJ / 64), 256>>>(
        s, Wq, bq, Wk, bk, Wv, bv, Wqp, bqp, Wkp, bkp, Wvp, bvp);

    scatter_kernel<<<N_RESV, 256>>>(T);

    bias_gemm_kernel<<<NROWS / 128, 128>>>(z, Wb, bb);

    att_kernel<<<dim3(48, NHV), 256>>>(hwt);

    att_av_kernel<<<dim3(12, NHV), 320>>>();

    out_kernel<<<N_RESV, 384>>>(z, T);

    gemm64_kernel<<<dim3(N_RESV / 64, N_RESV / 64, SPLITK), 256>>>(
        concat_p, DCAT, Wo, CSV, part_p, CSV, KSLICE);

    reduce_kernel<<<(NROWS / 4 + 255) / 256, 256>>>(bo, out);
}

// round 14
// speedup vs baseline: 1.2612x; 1.0774x over previous
#include <cuda_runtime.h>
#include <math.h>

#define N_RESV 384
#define CSV    384
#define CZV    128
#define NHV    12
#define CHV    16
#define NQPV   4
#define NPVV   8
#define DPROJ  1152
#define DCAT   2112
#define NROWS  (N_RESV * N_RESV)
#define SPLITK 4
#define KSLICE (DCAT / SPLITK)   // 528

typedef unsigned long long ull;

__device__ __forceinline__ ull pack2(float x, float y) {
    ull r; asm("mov.b64 %0, {%1,%2};" : "=l"(r) : "f"(x), "f"(y)); return r;
}
__device__ __forceinline__ ull ffma2(ull a, ull b, ull c) {
    ull d; asm("fma.rn.f32x2 %0, %1, %2, %3;" : "=l"(d) : "l"(a), "l"(b), "l"(c)); return d;
}
__device__ __forceinline__ float2 unpack2(ull p) {
    float x, y; asm("mov.b64 {%0,%1}, %2;" : "=f"(x), "=f"(y) : "l"(p));
    return make_float2(x, y);
}
__device__ __forceinline__ unsigned smem_u32(const void* p) {
    unsigned a;
    asm("{ .reg .u64 t; cvta.to.shared.u64 t, %1; cvt.u32.u64 %0, t; }"
        : "=r"(a) : "l"(p));
    return a;
}

// ---------------- scratch ----------------------------------------------------
__device__ float g_raw [N_RESV * DPROJ];
__device__ float g_q [NHV * N_RESV * CHV];
__device__ float g_k [NHV * N_RESV * CHV];
__device__ float g_v [NHV * N_RESV * CHV];
__device__ float g_tqp[NHV * NQPV * N_RESV * 3];
__device__ float g_tkp[NHV * NQPV * N_RESV * 3];
__device__ float g_tvp[NHV * NPVV * N_RESV * 3];
__device__ float g_bias[NHV * NROWS];
__device__ float g_att [NHV * NROWS];
__device__ float g_av  [NHV * N_RESV * 40];
__device__ float g_concat[N_RESV * DCAT];
__device__ float g_part[SPLITK * N_RESV * N_RESV];

// ---------- projection GEMM reading raw weight matrices directly -------------
__global__ void proj_gemm_kernel(
    const float* __restrict__ s,
    const float* Wq, const float* bq, const float* Wk, const float* bk,
    const float* Wv, const float* bv, const float* Wqp, const float* bqp,
    const float* Wkp, const float* bkp, const float* Wvp, const float* bvp)
{
    __shared__ float sA[16][36];
    __shared__ float sB[16][68];
    int i0 = blockIdx.x * 32;
    int o0 = blockIdx.y * 64;

    int t  = threadIdx.x;
    int tc = t & 15;
    int tr = t >> 4;

    int ar = t >> 2;
    int ak = (t & 3) * 4;
    int bk2 = t >> 4;
    int bn = (t & 15) * 4;

    int d = o0 + bn;
    const float* wsrc; const float* bsrc; int ldwS, colS;
    if      (d < 192)  { wsrc = Wq;  bsrc = bq;  ldwS = 192; colS = d; }
    else if (d < 384)  { wsrc = Wk;  bsrc = bk;  ldwS = 192; colS = d - 192; }
    else if (d < 576)  { wsrc = Wv;  bsrc = bv;  ldwS = 192; colS = d - 384; }
    else if (d < 720)  { wsrc = Wqp; bsrc = bqp; ldwS = 144; colS = d - 576; }
    else if (d < 864)  { wsrc = Wkp; bsrc = bkp; ldwS = 144; colS = d - 720; }
    else               { wsrc = Wvp; bsrc = bvp; ldwS = 288; colS = d - 864; }

    ull acc2[2][2];
    acc2[0][0] = acc2[0][1] = acc2[1][0] = acc2[1][1] = 0ull;

    for (int kk = 0; kk < CSV; kk += 16) {
        __syncthreads();
        if (t < 128) {
            float4 av = *(const float4*)&s[(size_t)(i0 + ar) * CSV + kk + ak];
            sA[ak + 0][ar] = av.x;
            sA[ak + 1][ar] = av.y;
            sA[ak + 2][ar] = av.z;
            sA[ak + 3][ar] = av.w;
        }
        float4 bv4 = *(const float4*)&wsrc[(size_t)(kk + bk2) * ldwS + colS];
        *(float4*)&sB[bk2][bn] = bv4;
        __syncthreads();
#pragma unroll
        for (int k = 0; k < 16; k++) {
            float2 a = *(const float2*)&sA[k][tr * 2];
            ulonglong2 b2 = *(const ulonglong2*)&sB[k][tc * 4];
            ull a0 = pack2(a.x, a.x);
            ull a1 = pack2(a.y, a.y);
            acc2[0][0] = ffma2(a0, b2.x, acc2[0][0]);
            acc2[0][1] = ffma2(a0, b2.y, acc2[0][1]);
            acc2[1][0] = ffma2(a1, b2.x, acc2[1][0]);
            acc2[1][1] = ffma2(a1, b2.y, acc2[1][1]);
        }
    }

    float4 bb4 = *(const float4*)&bsrc[colS];
#pragma unroll
    for (int i = 0; i < 2; i++) {
        float2 lo = unpack2(acc2[i][0]);
        float2 hi = unpack2(acc2[i][1]);
        float* crow = &g_raw[(size_t)(i0 + tr * 2 + i) * DPROJ + o0 + tc * 4];
        *(float4*)crow = make_float4(lo.x + bb4.x, lo.y + bb4.y,
                                     hi.x + bb4.z, hi.y + bb4.w);
    }
}

// ---------- register-tiled GEMM: 64x64 tile, 4x4 per thread (final) ----------
__global__ void gemm64_kernel(const float* __restrict__ A, int lda,
                              const float* __restrict__ W, int ldw,
                              float* __restrict__ C, int ldc, int kLen)
{
    __shared__ float sA[16][68];
    __shared__ float sB[16][68];
    int i0 = blockIdx.x * 64;
    int o0 = blockIdx.y * 64;
    int k0 = blockIdx.z * kLen;
    C += (size_t)blockIdx.z * (size_t)(gridDim.x * 64) * ldc;

    int t  = threadIdx.x;
    int tc = t & 15;
    int tr = t >> 4;

    int ar = t >> 2;
    int ak = (t & 3) * 4;
    int bk = t >> 4;
    int bn = (t & 15) * 4;

    ull acc2[4][2];
#pragma unroll
    for (int i = 0; i < 4; i++) { acc2[i][0] = 0ull; acc2[i][1] = 0ull; }

    for (int kk = 0; kk < kLen; kk += 16) {
        __syncthreads();
        float4 av = *(const float4*)&A[(size_t)(i0 + ar) * lda + k0 + kk + ak];
        sA[ak + 0][ar] = av.x;
        sA[ak + 1][ar] = av.y;
        sA[ak + 2][ar] = av.z;
        sA[ak + 3][ar] = av.w;
        float4 bv = *(const float4*)&W[(size_t)(k0 + kk + bk) * ldw + o0 + bn];
        *(float4*)&sB[bk][bn] = bv;
        __syncthreads();
#pragma unroll
        for (int k = 0; k < 16; k++) {
            float4 a = *(const float4*)&sA[k][tr * 4];
            ulonglong2 b2 = *(const ulonglong2*)&sB[k][tc * 4];
            ull a0 = pack2(a.x, a.x);
            ull a1 = pack2(a.y, a.y);
            ull a2 = pack2(a.z, a.z);
            ull a3 = pack2(a.w, a.w);
            acc2[0][0] = ffma2(a0, b2.x, acc2[0][0]);
            acc2[0][1] = ffma2(a0, b2.y, acc2[0][1]);
            acc2[1][0] = ffma2(a1, b2.x, acc2[1][0]);
            acc2[1][1] = ffma2(a1, b2.y, acc2[1][1]);
            acc2[2][0] = ffma2(a2, b2.x, acc2[2][0]);
            acc2[2][1] = ffma2(a2, b2.y, acc2[2][1]);
            acc2[3][0] = ffma2(a3, b2.x, acc2[3][0]);
            acc2[3][1] = ffma2(a3, b2.y, acc2[3][1]);
        }
    }

#pragma unroll
    for (int i = 0; i < 4; i++) {
        float2 lo = unpack2(acc2[i][0]);
        float2 hi = unpack2(acc2[i][1]);
        float* crow = &C[(size_t)(i0 + tr * 4 + i) * ldc + o0 + tc * 4];
        *(float4*)crow = make_float4(lo.x, lo.y, hi.x, hi.y);
    }
}

// ---------------- split-K reduce + bias (float4) -----------------------------
__global__ void reduce_kernel(const float* __restrict__ bias,
                              float* __restrict__ out)
{
    int idx = blockIdx.x * blockDim.x + threadIdx.x;
    if (idx >= NROWS / 4) return;
    const float4* p = (const float4*)g_part;
    float4 a = p[idx];
    float4 b = p[idx + NROWS / 4];
    float4 c = p[idx + NROWS / 2];
    float4 d = p[idx + 3 * NROWS / 4];
    int col = (idx % (N_RESV / 4)) * 4;
    float4 bv = *(const float4*)&bias[col];
    float4 o;
    o.x = a.x + b.x + c.x + d.x + bv.x;
    o.y = a.y + b.y + c.y + d.y + bv.y;
    o.z = a.z + b.z + c.z + d.z + bv.z;
    o.w = a.w + b.w + c.w + d.w + bv.w;
    ((float4*)out)[idx] = o;
}

// ---------------- kernel 3: scatter projections + transform points -----------
__global__ void scatter_kernel(const float* __restrict__ T)
{
    int i = blockIdx.x;
    const float* raw = g_raw + (size_t)i * DPROJ;
    const float* Ti  = T + (size_t)i * 16;

    for (int t = threadIdx.x; t < 768; t += blockDim.x) {
        if (t < 576) {
            int kind = t / 192, d = t % 192;
            int h = d / 16, c = d % 16;
            float v = raw[kind * 192 + d];
            if (kind == 0) v *= 0.25f;
            float* dst = (kind == 0) ? g_q : ((kind == 1) ? g_k : g_v);
            dst[(h * N_RESV + i) * CHV + c] = v;
        } else {
            int t2 = t - 576;
            int kind, hp, P, base;
            if      (t2 < 48)  { kind = 0; hp = t2;       P = NQPV; base = 576; }
            else if (t2 < 96)  { kind = 1; hp = t2 - 48;  P = NQPV; base = 720; }
            else               { kind = 2; hp = t2 - 96;  P = NPVV; base = 864; }
            int HP = NHV * P;
            float px = raw[base + 0 * HP + hp];
            float py = raw[base + 1 * HP + hp];
            float pz = raw[base + 2 * HP + hp];
            float ox = Ti[0] * px + Ti[1] * py + Ti[2]  * pz + Ti[3];
            float oy = Ti[4] * px + Ti[5] * py + Ti[6]  * pz + Ti[7];
            float oz = Ti[8] * px + Ti[9] * py + Ti[10] * pz + Ti[11];
            float* dst = (kind == 0) ? g_tqp : ((kind == 1) ? g_tkp : g_tvp);
            float* o = dst + ((size_t)hp * N_RESV + i) * 3;
            o[0] = ox; o[1] = oy; o[2] = oz;
        }
    }
}

// ---------------- kernel 4: bias = z @ Wb + bb (cp.async double-buffer) ------
__global__ void __launch_bounds__(128) bias_gemm_kernel(
    const float* __restrict__ z,
    const float* __restrict__ Wb,
    const float* __restrict__ bb)
{
    __shared__ float2 sz[2][128 * 17];
    __shared__ ull    swp[NHV * 64];
    int t = threadIdx.x;
    int r0 = blockIdx.x * 128;

    unsigned sbase0 = smem_u32(&sz[0][0]);
    unsigned sbase1 = smem_u32(&sz[1][0]);

    for (int idx = t; idx < NHV * 64; idx += 128) {
        int h = idx >> 6, q = idx & 63;
        swp[idx] = pack2(Wb[(2 * q) * NHV + h], Wb[(2 * q + 1) * NHV + h]);
    }

#pragma unroll
    for (int c0 = 0; c0 < 2; c0++) {
        unsigned sb = c0 ? sbase1 : sbase0;
        int ct = c0 * 32;
#pragma unroll
        for (int k = 0; k < 16; k++) {
            int idx = t + (k << 7);
            int row = idx >> 4, q = idx & 15;
            unsigned sa = sb + row * 136 + q * 8;
            const float* g = &z[(size_t)(r0 + row) * CZV + ct + q * 2];
            asm volatile("cp.async.ca.shared.global [%0], [%1], 8;\n"
                         :: "r"(sa), "l"(g));
        }
        asm volatile("cp.async.commit_group;\n");
    }

    ull acc[NHV];
#pragma unroll
    for (int h = 0; h < NHV; h++) acc[h] = 0ull;

#pragma unroll
    for (int c = 0; c < 4; c++) {
        if (c < 3) asm volatile("cp.async.wait_group 1;\n" ::: "memory");
        else       asm volatile("cp.async.wait_group 0;\n" ::: "memory");
        __syncthreads();
        const float2* zrow = &sz[c & 1][t * 17];
        int cbase = c << 4;
#pragma unroll
        for (int q = 0; q < 16; q++) {
            ull zp = *reinterpret_cast<const ull*>(&zrow[q]);
#pragma unroll
            for (int h = 0; h < NHV; h++)
                acc[h] = ffma2(zp, swp[(h << 6) + cbase + q], acc[h]);
        }
        if (c < 2) {
            __syncthreads();
            unsigned sb = (c & 1) ? sbase1 : sbase0;
            int ct = (c + 2) * 32;
#pragma unroll
            for (int k = 0; k < 16; k++) {
                int idx = t + (k << 7);
                int row = idx >> 4, q = idx & 15;
                unsigned sa = sb + row * 136 + q * 8;
                const float* g = &z[(size_t)(r0 + row) * CZV + ct + q * 2];
                asm volatile("cp.async.ca.shared.global [%0], [%1], 8;\n"
                             :: "r"(sa), "l"(g));
            }
            asm volatile("cp.async.commit_group;\n");
        }
    }

    int row = r0 + t;
#pragma unroll
    for (int h = 0; h < NHV; h++) {
        float2 v = unpack2(acc[h]);
        g_bias[(size_t)h * NROWS + row] = v.x + v.y + bb[h];
    }
}

// ---------------- kernel 5: logits + softmax, K-in-registers -----------------
// grid (24, 12), block 384. Thread j owns column j; 16 residues per block.
__global__ void __launch_bounds__(384) att_kernel(const float* __restrict__ head_weights)
{
    int h = blockIdx.y;
    int i0 = blockIdx.x * 16;
    __shared__ float sq  [16][16];
    __shared__ float sqp [16][12];
    __shared__ float slog[16][N_RESV];   // 24 KB

    int t = threadIdx.x;

    for (int idx = t; idx < 448; idx += 384) {
        if (idx < 256) {
            int iw = idx >> 4, c = idx & 15;
            sq[iw][c] = g_q[(h * N_RESV + i0 + iw) * CHV + c];
        } else {
            int u2 = idx - 256, iw = u2 / 12, u = u2 % 12, p = u / 3, d = u % 3;
            sqp[iw][u] = g_tqp[((h * NQPV + p) * N_RESV + i0 + iw) * 3 + d];
        }
    }

    float hw = head_weights[h];
    float gamma = (hw > 20.f) ? hw : log1pf(expf(hw));
    const float wc = 0.23570226039551584f;
    const float wl = 0.57735026918962576f;
    float coef = gamma * wc * 0.5f;

    // thread j: K row + KP into registers
    int j = t;
    const float4* kr = (const float4*)&g_k[(h * N_RESV + j) * CHV];
    float4 k0 = kr[0], k1 = kr[1], k2 = kr[2], k3 = kr[3];
    float kp[12];
#pragma unroll
    for (int p = 0; p < NQPV; p++) {
        const float* kps = &g_tkp[((h * NQPV + p) * N_RESV + j) * 3];
        kp[p * 3 + 0] = kps[0];
        kp[p * 3 + 1] = kps[1];
        kp[p * 3 + 2] = kps[2];
    }
    __syncthreads();

    const float* bcol = &g_bias[(size_t)h * NROWS + (size_t)i0 * N_RESV + j];
#pragma unroll 4
    for (int i = 0; i < 16; i++) {
        const float* q = sq[i];
        float qk = q[0]  * k0.x + q[1]  * k0.y + q[2]  * k0.z + q[3]  * k0.w
                 + q[4]  * k1.x + q[5]  * k1.y + q[6]  * k1.z + q[7]  * k1.w
                 + q[8]  * k2.x + q[9]  * k2.y + q[10] * k2.z + q[11] * k2.w
                 + q[12] * k3.x + q[13] * k3.y + q[14] * k3.z + q[15] * k3.w;
        float d2 = 0.f;
#pragma unroll
        for (int p = 0; p < NQPV; p++) {
            float dx = sqp[i][p * 3 + 0] - kp[p * 3 + 0];
            float dy = sqp[i][p * 3 + 1] - kp[p * 3 + 1];
            float dz = sqp[i][p * 3 + 2] - kp[p * 3 + 2];
            d2 += dx * dx + dy * dy + dz * dz;
        }
        slog[i][j] = wl * (qk + bcol[(size_t)i * N_RESV] - coef * d2);
    }
    __syncthreads();

    // softmax: warps 0..11 take rows w, w+12 (w<4)
    int w = t >> 5, lane = t & 31;
    for (int rr = w; rr < 16; rr += 12) {
        float m = -1e30f;
#pragma unroll
        for (int r = 0; r < 12; r++) m = fmaxf(m, slog[rr][lane + r * 32]);
#pragma unroll
        for (int o = 16; o; o >>= 1) m = fmaxf(m, __shfl_xor_sync(0xffffffffu, m, o));
        float ss = 0.f;
#pragma unroll
        for (int r = 0; r < 12; r++) {
            float e = expf(slog[rr][lane + r * 32] - m);
            slog[rr][lane + r * 32] = e;
            ss += e;
        }
#pragma unroll
        for (int o = 16; o; o >>= 1) ss += __shfl_xor_sync(0xffffffffu, ss, o);
        float inv = 1.f / ss;
        float* arow = &g_att[(size_t)h * NROWS + (size_t)(i0 + rr) * N_RESV];
#pragma unroll
        for (int r = 0; r < 12; r++)
            arow[lane + r * 32] = slog[rr][lane + r * 32] * inv;
    }
}

// ---------------- kernel 6: per-head GEMM  att[h] @ [v|vp], f32x2 ------------
__global__ void att_av_kernel()
{
    int h = blockIdx.y;
    int i0 = blockIdx.x * 32;
    __shared__ float satt[32][65];
    __shared__ float sx[64][44];
    int t = threadIdx.x;
    int r  = t / 10;
    int c0 = (t % 10) * 4;
    ull acc2[2];
    acc2[0] = 0ull; acc2[1] = 0ull;

    for (int j0 = 0; j0 < N_RESV; j0 += 64) {
        __syncthreads();
        for (int idx = t; idx < 32 * 16; idx += 320) {
            int row = idx >> 4, v4 = idx & 15;
            float4 v = *(const float4*)&g_att[((size_t)h * N_RESV + i0 + row) * N_RESV + j0 + v4 * 4];
            float* dst = &satt[row][v4 * 4];
            dst[0] = v.x; dst[1] = v.y; dst[2] = v.z; dst[3] = v.w;
        }
        for (int idx = t; idx < 64 * 40; idx += 320) {
            int j = idx / 40, col = idx % 40;
            float v;
            if (col < 16) v = g_v[(h * N_RESV + j0 + j) * CHV + col];
            else {
                int u = col - 16, p = u / 3, d = u % 3;
                v = g_tvp[((h * NPVV + p) * N_RESV + j0 + j) * 3 + d];
            }
            sx[j][col] = v;
        }
        __syncthreads();
#pragma unroll 4
        for (int jj = 0; jj < 64; jj++) {
            float a = satt[r][jj];
            ull ap = pack2(a, a);
            ulonglong2 xr = *(const ulonglong2*)&sx[jj][c0];
            acc2[0] = ffma2(ap, xr.x, acc2[0]);
            acc2[1] = ffma2(ap, xr.y, acc2[1]);
        }
    }
    float2 lo = unpack2(acc2[0]);
    float2 hi = unpack2(acc2[1]);
    float* orow = &g_av[((size_t)h * N_RESV + i0 + r) * 40 + c0];
    *(float4*)orow = make_float4(lo.x, lo.y, hi.x, hi.y);
}

// ---------------- kernel 7: pairwise GEMM + finalize (direct-LDG, f32x2) -----
__global__ void out_kernel(const float* __restrict__ z,
                           const float* __restrict__ T)
{
    int i = blockIdx.x;
    __shared__ float att[NHV][N_RESV];
    int t = threadIdx.x;

    for (int idx = t; idx < NHV * N_RESV / 4; idx += 384) {
        int h = idx / (N_RESV / 4), q = idx % (N_RESV / 4);
        float4 v = *(const float4*)&g_att[((size_t)h * N_RESV + i) * N_RESV + q * 4];
        *(float4*)&att[h][q * 4] = v;
    }
    __syncthreads();

    int h  = t >> 5;
    int c4 = t & 31;
    const ulonglong2* zbase = (const ulonglong2*)(z + (size_t)i * N_RESV * CZV) + c4;
    const float* arow = att[h];

    ull acc01 = 0ull, acc23 = 0ull;
#pragma unroll 4
    for (int j = 0; j < N_RESV; j++) {
        float a = arow[j];
        ull ap = pack2(a, a);
        ulonglong2 zp = __ldg(zbase + (size_t)j * 32);
        acc01 = ffma2(ap, zp.x, acc01);
        acc23 = ffma2(ap, zp.y, acc23);
    }
    float2 lo = unpack2(acc01);
    float2 hi = unpack2(acc23);
    float* crow = g_concat + (size_t)i * DCAT;
    *(float4*)&crow[576 + h * CZV + c4 * 4] = make_float4(lo.x, lo.y, hi.x, hi.y);

    if (t < 192) {
        int hh = t / 16, cc = t % 16;
        crow[hh * 16 + cc] = g_av[((size_t)hh * N_RESV + i) * 40 + cc];
    }
    const float* Ti = T + (size_t)i * 16;
    if (t < 96) {
        int hh = t / 8, p = t % 8;
        const float* av = &g_av[((size_t)hh * N_RESV + i) * 40 + 16 + p * 3];
        float px = av[0] - Ti[3];
        float py = av[1] - Ti[7];
        float pz = av[2] - Ti[11];
        float ox = Ti[0] * px + Ti[4] * py + Ti[8]  * pz;
        float oy = Ti[1] * px + Ti[5] * py + Ti[9]  * pz;
        float oz = Ti[2] * px + Ti[6] * py + Ti[10] * pz;
        crow[192 +   0 + hh * 8 + p] = ox;
        crow[192 +  96 + hh * 8 + p] = oy;
        crow[192 + 192 + hh * 8 + p] = oz;
        crow[480 + hh * 8 + p] = sqrtf(ox * ox + oy * oy + oz * oz);
    }
}

// ---------------- launch ------------------------------------------------------
extern "C" void kernel_launch(void* const* d_in, const int* in_sizes, int n_in,
                              void* d_out, int out_size)
{
    const float* s   = (const float*)d_in[0];
    const float* z   = (const float*)d_in[1];
    const float* T   = (const float*)d_in[2];
    const float* Wq  = (const float*)d_in[3];
    const float* bq  = (const float*)d_in[4];
    const float* Wk  = (const float*)d_in[5];
    const float* bk  = (const float*)d_in[6];
    const float* Wv  = (const float*)d_in[7];
    const float* bv  = (const float*)d_in[8];
    const float* Wqp = (const float*)d_in[9];
    const float* bqp = (const float*)d_in[10];
    const float* Wkp = (const float*)d_in[11];
    const float* bkp = (const float*)d_in[12];
    const float* Wvp = (const float*)d_in[13];
    const float* bvp = (const float*)d_in[14];
    const float* Wb  = (const float*)d_in[15];
    const float* bb  = (const float*)d_in[16];
    const float* Wo  = (const float*)d_in[17];
    const float* bo  = (const float*)d_in[18];
    const float* hwt = (const float*)d_in[19];

    float* out = (float*)d_out;

    float* concat_p; cudaGetSymbolAddress((void**)&concat_p, g_concat);
    float* part_p;   cudaGetSymbolAddress((void**)&part_p,   g_part);

    proj_gemm_kernel<<<dim3(N_RESV / 32, DPROJ / 64), 256>>>(
        s, Wq, bq, Wk, bk, Wv, bv, Wqp, bqp, Wkp, bkp, Wvp, bvp);

    scatter_kernel<<<N_RESV, 256>>>(T);

    bias_gemm_kernel<<<NROWS / 128, 128>>>(z, Wb, bb);

    att_kernel<<<dim3(24, NHV), 384>>>(hwt);

    att_av_kernel<<<dim3(12, NHV), 320>>>();

    out_kernel<<<N_RESV, 384>>>(z, T);

    gemm64_kernel<<<dim3(N_RESV / 64, N_RESV / 64, SPLITK), 256>>>(
        concat_p, DCAT, Wo, CSV, part_p, CSV, KSLICE);

    reduce_kernel<<<(NROWS / 4 + 255) / 256, 256>>>(bo, out);
}

// round 15
// speedup vs baseline: 1.3198x; 1.0464x over previous
#include <cuda_runtime.h>
#include <math.h>

#define N_RESV 384
#define CSV    384
#define CZV    128
#define NHV    12
#define CHV    16
#define NQPV   4
#define NPVV   8
#define DPROJ  1152
#define DCAT   2112
#define NROWS  (N_RESV * N_RESV)
#define SPLITK 11
#define KSLICE (DCAT / SPLITK)   // 192

typedef unsigned long long ull;

__device__ __forceinline__ ull pack2(float x, float y) {
    ull r; asm("mov.b64 %0, {%1,%2};" : "=l"(r) : "f"(x), "f"(y)); return r;
}
__device__ __forceinline__ ull ffma2(ull a, ull b, ull c) {
    ull d; asm("fma.rn.f32x2 %0, %1, %2, %3;" : "=l"(d) : "l"(a), "l"(b), "l"(c)); return d;
}
__device__ __forceinline__ float2 unpack2(ull p) {
    float x, y; asm("mov.b64 {%0,%1}, %2;" : "=f"(x), "=f"(y) : "l"(p));
    return make_float2(x, y);
}
__device__ __forceinline__ unsigned smem_u32(const void* p) {
    unsigned a;
    asm("{ .reg .u64 t; cvta.to.shared.u64 t, %1; cvt.u32.u64 %0, t; }"
        : "=r"(a) : "l"(p));
    return a;
}

// ---------------- scratch ----------------------------------------------------
__device__ float g_raw [N_RESV * DPROJ];
__device__ float g_q [NHV * N_RESV * CHV];
__device__ float g_k [NHV * N_RESV * CHV];
__device__ float g_v [NHV * N_RESV * CHV];
__device__ float g_tqp[NHV * NQPV * N_RESV * 3];
__device__ float g_tkp[NHV * NQPV * N_RESV * 3];
__device__ float g_tvp[NHV * NPVV * N_RESV * 3];
__device__ float g_bias[NHV * NROWS];
__device__ float g_att [NHV * NROWS];
__device__ float g_av  [NHV * N_RESV * 40];
__device__ float g_concat[N_RESV * DCAT];
__device__ float g_part[SPLITK * N_RESV * N_RESV];

// ---------- projection GEMM reading raw weight matrices directly -------------
__global__ void proj_gemm_kernel(
    const float* __restrict__ s,
    const float* Wq, const float* bq, const float* Wk, const float* bk,
    const float* Wv, const float* bv, const float* Wqp, const float* bqp,
    const float* Wkp, const float* bkp, const float* Wvp, const float* bvp)
{
    __shared__ float sA[16][36];
    __shared__ float sB[16][68];
    int i0 = blockIdx.x * 32;
    int o0 = blockIdx.y * 64;

    int t  = threadIdx.x;
    int tc = t & 15;
    int tr = t >> 4;

    int ar = t >> 2;
    int ak = (t & 3) * 4;
    int bk2 = t >> 4;
    int bn = (t & 15) * 4;

    int d = o0 + bn;
    const float* wsrc; const float* bsrc; int ldwS, colS;
    if      (d < 192)  { wsrc = Wq;  bsrc = bq;  ldwS = 192; colS = d; }
    else if (d < 384)  { wsrc = Wk;  bsrc = bk;  ldwS = 192; colS = d - 192; }
    else if (d < 576)  { wsrc = Wv;  bsrc = bv;  ldwS = 192; colS = d - 384; }
    else if (d < 720)  { wsrc = Wqp; bsrc = bqp; ldwS = 144; colS = d - 576; }
    else if (d < 864)  { wsrc = Wkp; bsrc = bkp; ldwS = 144; colS = d - 720; }
    else               { wsrc = Wvp; bsrc = bvp; ldwS = 288; colS = d - 864; }

    ull acc2[2][2];
    acc2[0][0] = acc2[0][1] = acc2[1][0] = acc2[1][1] = 0ull;

    for (int kk = 0; kk < CSV; kk += 16) {
        __syncthreads();
        if (t < 128) {
            float4 av = *(const float4*)&s[(size_t)(i0 + ar) * CSV + kk + ak];
            sA[ak + 0][ar] = av.x;
            sA[ak + 1][ar] = av.y;
            sA[ak + 2][ar] = av.z;
            sA[ak + 3][ar] = av.w;
        }
        float4 bv4 = *(const float4*)&wsrc[(size_t)(kk + bk2) * ldwS + colS];
        *(float4*)&sB[bk2][bn] = bv4;
        __syncthreads();
#pragma unroll
        for (int k = 0; k < 16; k++) {
            float2 a = *(const float2*)&sA[k][tr * 2];
            ulonglong2 b2 = *(const ulonglong2*)&sB[k][tc * 4];
            ull a0 = pack2(a.x, a.x);
            ull a1 = pack2(a.y, a.y);
            acc2[0][0] = ffma2(a0, b2.x, acc2[0][0]);
            acc2[0][1] = ffma2(a0, b2.y, acc2[0][1]);
            acc2[1][0] = ffma2(a1, b2.x, acc2[1][0]);
            acc2[1][1] = ffma2(a1, b2.y, acc2[1][1]);
        }
    }

    float4 bb4 = *(const float4*)&bsrc[colS];
#pragma unroll
    for (int i = 0; i < 2; i++) {
        float2 lo = unpack2(acc2[i][0]);
        float2 hi = unpack2(acc2[i][1]);
        float* crow = &g_raw[(size_t)(i0 + tr * 2 + i) * DPROJ + o0 + tc * 4];
        *(float4*)crow = make_float4(lo.x + bb4.x, lo.y + bb4.y,
                                     hi.x + bb4.z, hi.y + bb4.w);
    }
}

// ---------- register-tiled GEMM: 64x64 tile, 4x4 per thread (final) ----------
__global__ void gemm64_kernel(const float* __restrict__ A, int lda,
                              const float* __restrict__ W, int ldw,
                              float* __restrict__ C, int ldc, int kLen)
{
    __shared__ float sA[16][68];
    __shared__ float sB[16][68];
    int i0 = blockIdx.x * 64;
    int o0 = blockIdx.y * 64;
    int k0 = blockIdx.z * kLen;
    C += (size_t)blockIdx.z * (size_t)(gridDim.x * 64) * ldc;

    int t  = threadIdx.x;
    int tc = t & 15;
    int tr = t >> 4;

    int ar = t >> 2;
    int ak = (t & 3) * 4;
    int bk = t >> 4;
    int bn = (t & 15) * 4;

    ull acc2[4][2];
#pragma unroll
    for (int i = 0; i < 4; i++) { acc2[i][0] = 0ull; acc2[i][1] = 0ull; }

    for (int kk = 0; kk < kLen; kk += 16) {
        __syncthreads();
        float4 av = *(const float4*)&A[(size_t)(i0 + ar) * lda + k0 + kk + ak];
        sA[ak + 0][ar] = av.x;
        sA[ak + 1][ar] = av.y;
        sA[ak + 2][ar] = av.z;
        sA[ak + 3][ar] = av.w;
        float4 bv = *(const float4*)&W[(size_t)(k0 + kk + bk) * ldw + o0 + bn];
        *(float4*)&sB[bk][bn] = bv;
        __syncthreads();
#pragma unroll
        for (int k = 0; k < 16; k++) {
            float4 a = *(const float4*)&sA[k][tr * 4];
            ulonglong2 b2 = *(const ulonglong2*)&sB[k][tc * 4];
            ull a0 = pack2(a.x, a.x);
            ull a1 = pack2(a.y, a.y);
            ull a2 = pack2(a.z, a.z);
            ull a3 = pack2(a.w, a.w);
            acc2[0][0] = ffma2(a0, b2.x, acc2[0][0]);
            acc2[0][1] = ffma2(a0, b2.y, acc2[0][1]);
            acc2[1][0] = ffma2(a1, b2.x, acc2[1][0]);
            acc2[1][1] = ffma2(a1, b2.y, acc2[1][1]);
            acc2[2][0] = ffma2(a2, b2.x, acc2[2][0]);
            acc2[2][1] = ffma2(a2, b2.y, acc2[2][1]);
            acc2[3][0] = ffma2(a3, b2.x, acc2[3][0]);
            acc2[3][1] = ffma2(a3, b2.y, acc2[3][1]);
        }
    }

#pragma unroll
    for (int i = 0; i < 4; i++) {
        float2 lo = unpack2(acc2[i][0]);
        float2 hi = unpack2(acc2[i][1]);
        float* crow = &C[(size_t)(i0 + tr * 4 + i) * ldc + o0 + tc * 4];
        *(float4*)crow = make_float4(lo.x, lo.y, hi.x, hi.y);
    }
}

// ---------------- split-K reduce + bias (float4) -----------------------------
__global__ void reduce_kernel(const float* __restrict__ bias,
                              float* __restrict__ out)
{
    int idx = blockIdx.x * blockDim.x + threadIdx.x;
    if (idx >= NROWS / 4) return;
    const float4* p = (const float4*)g_part;
    float4 acc = p[idx];
#pragma unroll
    for (int k = 1; k < SPLITK; k++) {
        float4 v = p[idx + (size_t)k * (NROWS / 4)];
        acc.x += v.x; acc.y += v.y; acc.z += v.z; acc.w += v.w;
    }
    int col = (idx % (N_RESV / 4)) * 4;
    float4 bv = *(const float4*)&bias[col];
    acc.x += bv.x; acc.y += bv.y; acc.z += bv.z; acc.w += bv.w;
    ((float4*)out)[idx] = acc;
}

// ---------------- kernel 3: scatter projections + transform points -----------
__global__ void scatter_kernel(const float* __restrict__ T)
{
    int i = blockIdx.x;
    const float* raw = g_raw + (size_t)i * DPROJ;
    const float* Ti  = T + (size_t)i * 16;

    for (int t = threadIdx.x; t < 768; t += blockDim.x) {
        if (t < 576) {
            int kind = t / 192, d = t % 192;
            int h = d / 16, c = d % 16;
            float v = raw[kind * 192 + d];
            if (kind == 0) v *= 0.25f;
            float* dst = (kind == 0) ? g_q : ((kind == 1) ? g_k : g_v);
            dst[(h * N_RESV + i) * CHV + c] = v;
        } else {
            int t2 = t - 576;
            int kind, hp, P, base;
            if      (t2 < 48)  { kind = 0; hp = t2;       P = NQPV; base = 576; }
            else if (t2 < 96)  { kind = 1; hp = t2 - 48;  P = NQPV; base = 720; }
            else               { kind = 2; hp = t2 - 96;  P = NPVV; base = 864; }
            int HP = NHV * P;
            float px = raw[base + 0 * HP + hp];
            float py = raw[base + 1 * HP + hp];
            float pz = raw[base + 2 * HP + hp];
            float ox = Ti[0] * px + Ti[1] * py + Ti[2]  * pz + Ti[3];
            float oy = Ti[4] * px + Ti[5] * py + Ti[6]  * pz + Ti[7];
            float oz = Ti[8] * px + Ti[9] * py + Ti[10] * pz + Ti[11];
            float* dst = (kind == 0) ? g_tqp : ((kind == 1) ? g_tkp : g_tvp);
            float* o = dst + ((size_t)hp * N_RESV + i) * 3;
            o[0] = ox; o[1] = oy; o[2] = oz;
        }
    }
}

// ---------------- kernel 4: bias = z @ Wb + bb (cp.async double-buffer) ------
__global__ void __launch_bounds__(128, 6) bias_gemm_kernel(
    const float* __restrict__ z,
    const float* __restrict__ Wb,
    const float* __restrict__ bb)
{
    __shared__ float2 sz[2][128 * 17];
    __shared__ ull    swp[NHV * 64];
    int t = threadIdx.x;
    int r0 = blockIdx.x * 128;

    unsigned sbase0 = smem_u32(&sz[0][0]);
    unsigned sbase1 = smem_u32(&sz[1][0]);

    for (int idx = t; idx < NHV * 64; idx += 128) {
        int h = idx >> 6, q = idx & 63;
        swp[idx] = pack2(Wb[(2 * q) * NHV + h], Wb[(2 * q + 1) * NHV + h]);
    }

#pragma unroll
    for (int c0 = 0; c0 < 2; c0++) {
        unsigned sb = c0 ? sbase1 : sbase0;
        int ct = c0 * 32;
#pragma unroll
        for (int k = 0; k < 16; k++) {
            int idx = t + (k << 7);
            int row = idx >> 4, q = idx & 15;
            unsigned sa = sb + row * 136 + q * 8;
            const float* g = &z[(size_t)(r0 + row) * CZV + ct + q * 2];
            asm volatile("cp.async.ca.shared.global [%0], [%1], 8;\n"
                         :: "r"(sa), "l"(g));
        }
        asm volatile("cp.async.commit_group;\n");
    }

    ull acc[NHV];
#pragma unroll
    for (int h = 0; h < NHV; h++) acc[h] = 0ull;

#pragma unroll
    for (int c = 0; c < 4; c++) {
        if (c < 3) asm volatile("cp.async.wait_group 1;\n" ::: "memory");
        else       asm volatile("cp.async.wait_group 0;\n" ::: "memory");
        __syncthreads();
        const float2* zrow = &sz[c & 1][t * 17];
        int cbase = c << 4;
#pragma unroll
        for (int q = 0; q < 16; q++) {
            ull zp = *reinterpret_cast<const ull*>(&zrow[q]);
#pragma unroll
            for (int h = 0; h < NHV; h++)
                acc[h] = ffma2(zp, swp[(h << 6) + cbase + q], acc[h]);
        }
        if (c < 2) {
            __syncthreads();
            unsigned sb = (c & 1) ? sbase1 : sbase0;
            int ct = (c + 2) * 32;
#pragma unroll
            for (int k = 0; k < 16; k++) {
                int idx = t + (k << 7);
                int row = idx >> 4, q = idx & 15;
                unsigned sa = sb + row * 136 + q * 8;
                const float* g = &z[(size_t)(r0 + row) * CZV + ct + q * 2];
                asm volatile("cp.async.ca.shared.global [%0], [%1], 8;\n"
                             :: "r"(sa), "l"(g));
            }
            asm volatile("cp.async.commit_group;\n");
        }
    }

    int row = r0 + t;
#pragma unroll
    for (int h = 0; h < NHV; h++) {
        float2 v = unpack2(acc[h]);
        g_bias[(size_t)h * NROWS + row] = v.x + v.y + bb[h];
    }
}

// ---------------- kernel 5: logits + softmax, K-in-registers -----------------
__global__ void __launch_bounds__(384) att_kernel(const float* __restrict__ head_weights)
{
    int h = blockIdx.y;
    int i0 = blockIdx.x * 16;
    __shared__ float sq  [16][16];
    __shared__ float sqp [16][12];
    __shared__ float slog[16][N_RESV];

    int t = threadIdx.x;

    for (int idx = t; idx < 448; idx += 384) {
        if (idx < 256) {
            int iw = idx >> 4, c = idx & 15;
            sq[iw][c] = g_q[(h * N_RESV + i0 + iw) * CHV + c];
        } else {
            int u2 = idx - 256, iw = u2 / 12, u = u2 % 12, p = u / 3, d = u % 3;
            sqp[iw][u] = g_tqp[((h * NQPV + p) * N_RESV + i0 + iw) * 3 + d];
        }
    }

    float hw = head_weights[h];
    float gamma = (hw > 20.f) ? hw : log1pf(expf(hw));
    const float wc = 0.23570226039551584f;
    const float wl = 0.57735026918962576f;
    float coef = gamma * wc * 0.5f;

    int j = t;
    const float4* kr = (const float4*)&g_k[(h * N_RESV + j) * CHV];
    float4 k0 = kr[0], k1 = kr[1], k2 = kr[2], k3 = kr[3];
    float kp[12];
#pragma unroll
    for (int p = 0; p < NQPV; p++) {
        const float* kps = &g_tkp[((h * NQPV + p) * N_RESV + j) * 3];
        kp[p * 3 + 0] = kps[0];
        kp[p * 3 + 1] = kps[1];
        kp[p * 3 + 2] = kps[2];
    }
    __syncthreads();

    const float* bcol = &g_bias[(size_t)h * NROWS + (size_t)i0 * N_RESV + j];
#pragma unroll 4
    for (int i = 0; i < 16; i++) {
        const float* q = sq[i];
        float qk = q[0]  * k0.x + q[1]  * k0.y + q[2]  * k0.z + q[3]  * k0.w
                 + q[4]  * k1.x + q[5]  * k1.y + q[6]  * k1.z + q[7]  * k1.w
                 + q[8]  * k2.x + q[9]  * k2.y + q[10] * k2.z + q[11] * k2.w
                 + q[12] * k3.x + q[13] * k3.y + q[14] * k3.z + q[15] * k3.w;
        float d2 = 0.f;
#pragma unroll
        for (int p = 0; p < NQPV; p++) {
            float dx = sqp[i][p * 3 + 0] - kp[p * 3 + 0];
            float dy = sqp[i][p * 3 + 1] - kp[p * 3 + 1];
            float dz = sqp[i][p * 3 + 2] - kp[p * 3 + 2];
            d2 += dx * dx + dy * dy + dz * dz;
        }
        slog[i][j] = wl * (qk + bcol[(size_t)i * N_RESV] - coef * d2);
    }
    __syncthreads();

    int w = t >> 5, lane = t & 31;
    for (int rr = w; rr < 16; rr += 12) {
        float m = -1e30f;
#pragma unroll
        for (int r = 0; r < 12; r++) m = fmaxf(m, slog[rr][lane + r * 32]);
#pragma unroll
        for (int o = 16; o; o >>= 1) m = fmaxf(m, __shfl_xor_sync(0xffffffffu, m, o));
        float ss = 0.f;
#pragma unroll
        for (int r = 0; r < 12; r++) {
            float e = expf(slog[rr][lane + r * 32] - m);
            slog[rr][lane + r * 32] = e;
            ss += e;
        }
#pragma unroll
        for (int o = 16; o; o >>= 1) ss += __shfl_xor_sync(0xffffffffu, ss, o);
        float inv = 1.f / ss;
        float* arow = &g_att[(size_t)h * NROWS + (size_t)(i0 + rr) * N_RESV];
#pragma unroll
        for (int r = 0; r < 12; r++)
            arow[lane + r * 32] = slog[rr][lane + r * 32] * inv;
    }
}

// ---------------- kernel 6: per-head GEMM  att[h] @ [v|vp], f32x2 ------------
__global__ void att_av_kernel()
{
    int h = blockIdx.y;
    int i0 = blockIdx.x * 32;
    __shared__ float satt[32][65];
    __shared__ float sx[64][44];
    int t = threadIdx.x;
    int r  = t / 10;
    int c0 = (t % 10) * 4;
    ull acc2[2];
    acc2[0] = 0ull; acc2[1] = 0ull;

    for (int j0 = 0; j0 < N_RESV; j0 += 64) {
        __syncthreads();
        for (int idx = t; idx < 32 * 16; idx += 320) {
            int row = idx >> 4, v4 = idx & 15;
            float4 v = *(const float4*)&g_att[((size_t)h * N_RESV + i0 + row) * N_RESV + j0 + v4 * 4];
            float* dst = &satt[row][v4 * 4];
            dst[0] = v.x; dst[1] = v.y; dst[2] = v.z; dst[3] = v.w;
        }
        for (int idx = t; idx < 64 * 40; idx += 320) {
            int j = idx / 40, col = idx % 40;
            float v;
            if (col < 16) v = g_v[(h * N_RESV + j0 + j) * CHV + col];
            else {
                int u = col - 16, p = u / 3, d = u % 3;
                v = g_tvp[((h * NPVV + p) * N_RESV + j0 + j) * 3 + d];
            }
            sx[j][col] = v;
        }
        __syncthreads();
#pragma unroll 4
        for (int jj = 0; jj < 64; jj++) {
            float a = satt[r][jj];
            ull ap = pack2(a, a);
            ulonglong2 xr = *(const ulonglong2*)&sx[jj][c0];
            acc2[0] = ffma2(ap, xr.x, acc2[0]);
            acc2[1] = ffma2(ap, xr.y, acc2[1]);
        }
    }
    float2 lo = unpack2(acc2[0]);
    float2 hi = unpack2(acc2[1]);
    float* orow = &g_av[((size_t)h * N_RESV + i0 + r) * 40 + c0];
    *(float4*)orow = make_float4(lo.x, lo.y, hi.x, hi.y);
}

// ---------------- kernel 7: pairwise GEMM + finalize (cp.async z) ------------
// block per i, 384 threads; z staged in smem chunks of 16 rows, depth-2.
#define ZROWS 16
__global__ void __launch_bounds__(384) out_kernel(const float* __restrict__ z,
                                                  const float* __restrict__ T)
{
    int i = blockIdx.x;
    __shared__ float att[NHV][N_RESV];       // 18 KB
    __shared__ float zb[2][ZROWS][132];      // 16.5 KB
    int t = threadIdx.x;

    unsigned zb0 = smem_u32(&zb[0][0][0]);
    unsigned zb1 = smem_u32(&zb[1][0][0]);
    const float* zsrc = z + (size_t)i * N_RESV * CZV;

    // issue chunk 0 and 1
#pragma unroll
    for (int c0 = 0; c0 < 2; c0++) {
        unsigned sb = c0 ? zb1 : zb0;
        for (int idx = t; idx < ZROWS * 32; idx += 384) {
            int row = idx >> 5, cq = idx & 31;
            unsigned sa = sb + (unsigned)(row * 132 + cq * 4) * 4u;
            const float* g = zsrc + (size_t)(c0 * ZROWS + row) * CZV + cq * 4;
            asm volatile("cp.async.cg.shared.global [%0], [%1], 16;\n"
                         :: "r"(sa), "l"(g));
        }
        asm volatile("cp.async.commit_group;\n");
    }

    for (int idx = t; idx < NHV * N_RESV / 4; idx += 384) {
        int h = idx / (N_RESV / 4), q = idx % (N_RESV / 4);
        float4 v = *(const float4*)&g_att[((size_t)h * N_RESV + i) * N_RESV + q * 4];
        *(float4*)&att[h][q * 4] = v;
    }

    int h  = t >> 5;
    int c4 = t & 31;
    const float* arow = att[h];

    ull acc01 = 0ull, acc23 = 0ull;
    const int NCHUNK = N_RESV / ZROWS;   // 24
    for (int c = 0; c < NCHUNK; c++) {
        if (c < NCHUNK - 1) asm volatile("cp.async.wait_group 1;\n" ::: "memory");
        else                asm volatile("cp.async.wait_group 0;\n" ::: "memory");
        __syncthreads();
        int b = c & 1;
        int j0 = c * ZROWS;
#pragma unroll
        for (int jj = 0; jj < ZROWS; jj++) {
            float a = arow[j0 + jj];
            ull ap = pack2(a, a);
            ulonglong2 zp = *(const ulonglong2*)&zb[b][jj][c4 * 4];
            acc01 = ffma2(ap, zp.x, acc01);
            acc23 = ffma2(ap, zp.y, acc23);
        }
        if (c < NCHUNK - 2) {
            __syncthreads();
            unsigned sb = (c & 1) ? zb1 : zb0;
            for (int idx = t; idx < ZROWS * 32; idx += 384) {
                int row = idx >> 5, cq = idx & 31;
                unsigned sa = sb + (unsigned)(row * 132 + cq * 4) * 4u;
                const float* g = zsrc + (size_t)((c + 2) * ZROWS + row) * CZV + cq * 4;
                asm volatile("cp.async.cg.shared.global [%0], [%1], 16;\n"
                             :: "r"(sa), "l"(g));
            }
            asm volatile("cp.async.commit_group;\n");
        }
    }
    float2 lo = unpack2(acc01);
    float2 hi = unpack2(acc23);
    float* crow = g_concat + (size_t)i * DCAT;
    *(float4*)&crow[576 + h * CZV + c4 * 4] = make_float4(lo.x, lo.y, hi.x, hi.y);

    if (t < 192) {
        int hh = t / 16, cc = t % 16;
        crow[hh * 16 + cc] = g_av[((size_t)hh * N_RESV + i) * 40 + cc];
    }
    const float* Ti = T + (size_t)i * 16;
    if (t < 96) {
        int hh = t / 8, p = t % 8;
        const float* av = &g_av[((size_t)hh * N_RESV + i) * 40 + 16 + p * 3];
        float px = av[0] - Ti[3];
        float py = av[1] - Ti[7];
        float pz = av[2] - Ti[11];
        float ox = Ti[0] * px + Ti[4] * py + Ti[8]  * pz;
        float oy = Ti[1] * px + Ti[5] * py + Ti[9]  * pz;
        float oz = Ti[2] * px + Ti[6] * py + Ti[10] * pz;
        crow[192 +   0 + hh * 8 + p] = ox;
        crow[192 +  96 + hh * 8 + p] = oy;
        crow[192 + 192 + hh * 8 + p] = oz;
        crow[480 + hh * 8 + p] = sqrtf(ox * ox + oy * oy + oz * oz);
    }
}

// ---------------- launch ------------------------------------------------------
extern "C" void kernel_launch(void* const* d_in, const int* in_sizes, int n_in,
                              void* d_out, int out_size)
{
    const float* s   = (const float*)d_in[0];
    const float* z   = (const float*)d_in[1];
    const float* T   = (const float*)d_in[2];
    const float* Wq  = (const float*)d_in[3];
    const float* bq  = (const float*)d_in[4];
    const float* Wk  = (const float*)d_in[5];
    const float* bk  = (const float*)d_in[6];
    const float* Wv  = (const float*)d_in[7];
    const float* bv  = (const float*)d_in[8];
    const float* Wqp = (const float*)d_in[9];
    const float* bqp = (const float*)d_in[10];
    const float* Wkp = (const float*)d_in[11];
    const float* bkp = (const float*)d_in[12];
    const float* Wvp = (const float*)d_in[13];
    const float* bvp = (const float*)d_in[14];
    const float* Wb  = (const float*)d_in[15];
    const float* bb  = (const float*)d_in[16];
    const float* Wo  = (const float*)d_in[17];
    const float* bo  = (const float*)d_in[18];
    const float* hwt = (const float*)d_in[19];

    float* out = (float*)d_out;

    float* concat_p; cudaGetSymbolAddress((void**)&concat_p, g_concat);
    float* part_p;   cudaGetSymbolAddress((void**)&part_p,   g_part);

    proj_gemm_kernel<<<dim3(N_RESV / 32, DPROJ / 64), 256>>>(
        s, Wq, bq, Wk, bk, Wv, bv, Wqp, bqp, Wkp, bkp, Wvp, bvp);

    scatter_kernel<<<N_RESV, 256>>>(T);

    bias_gemm_kernel<<<NROWS / 128, 128>>>(z, Wb, bb);

    att_kernel<<<dim3(24, NHV), 384>>>(hwt);

    att_av_kernel<<<dim3(12, NHV), 320>>>();

    out_kernel<<<N_RESV, 384>>>(z, T);

    gemm64_kernel<<<dim3(N_RESV / 64, N_RESV / 64, SPLITK), 256>>>(
        concat_p, DCAT, Wo, CSV, part_p, CSV, KSLICE);

    reduce_kernel<<<(NROWS / 4 + 255) / 256, 256>>>(bo, out);
}

// round 16
// speedup vs baseline: 1.4845x; 1.1248x over previous
#include <cuda_runtime.h>
#include <math.h>

#define N_RESV 384
#define CSV    384
#define CZV    128
#define NHV    12
#define CHV    16
#define NQPV   4
#define NPVV   8
#define DPROJ  1152
#define DCAT   2112
#define NROWS  (N_RESV * N_RESV)
#define SPLITK 11
#define KSLICE (DCAT / SPLITK)   // 192

typedef unsigned long long ull;

__device__ __forceinline__ ull pack2(float x, float y) {
    ull r; asm("mov.b64 %0, {%1,%2};" : "=l"(r) : "f"(x), "f"(y)); return r;
}
__device__ __forceinline__ ull ffma2(ull a, ull b, ull c) {
    ull d; asm("fma.rn.f32x2 %0, %1, %2, %3;" : "=l"(d) : "l"(a), "l"(b), "l"(c)); return d;
}
__device__ __forceinline__ float2 unpack2(ull p) {
    float x, y; asm("mov.b64 {%0,%1}, %2;" : "=f"(x), "=f"(y) : "l"(p));
    return make_float2(x, y);
}
__device__ __forceinline__ unsigned smem_u32(const void* p) {
    unsigned a;
    asm("{ .reg .u64 t; cvta.to.shared.u64 t, %1; cvt.u32.u64 %0, t; }"
        : "=r"(a) : "l"(p));
    return a;
}

// ---------------- scratch ----------------------------------------------------
__device__ float g_raw [N_RESV * DPROJ];
__device__ float g_q [NHV * N_RESV * CHV];
__device__ float g_k [NHV * N_RESV * CHV];
__device__ float g_v [NHV * N_RESV * CHV];
__device__ float g_tqp[NHV * NQPV * N_RESV * 3];
__device__ float g_tkp[NHV * NQPV * N_RESV * 3];
__device__ float g_tvp[NHV * NPVV * N_RESV * 3];
__device__ float g_bias[NHV * NROWS];
__device__ float g_att [NHV * NROWS];
__device__ float g_av  [NHV * N_RESV * 40];
__device__ float g_concat[N_RESV * DCAT];
__device__ float g_part[SPLITK * N_RESV * N_RESV];

// ---------- projection GEMM reading raw weight matrices directly -------------
__global__ void proj_gemm_kernel(
    const float* __restrict__ s,
    const float* Wq, const float* bq, const float* Wk, const float* bk,
    const float* Wv, const float* bv, const float* Wqp, const float* bqp,
    const float* Wkp, const float* bkp, const float* Wvp, const float* bvp)
{
    __shared__ float sA[16][36];
    __shared__ float sB[16][68];
    int i0 = blockIdx.x * 32;
    int o0 = blockIdx.y * 64;

    int t  = threadIdx.x;
    int tc = t & 15;
    int tr = t >> 4;

    int ar = t >> 2;
    int ak = (t & 3) * 4;
    int bk2 = t >> 4;
    int bn = (t & 15) * 4;

    int d = o0 + bn;
    const float* wsrc; const float* bsrc; int ldwS, colS;
    if      (d < 192)  { wsrc = Wq;  bsrc = bq;  ldwS = 192; colS = d; }
    else if (d < 384)  { wsrc = Wk;  bsrc = bk;  ldwS = 192; colS = d - 192; }
    else if (d < 576)  { wsrc = Wv;  bsrc = bv;  ldwS = 192; colS = d - 384; }
    else if (d < 720)  { wsrc = Wqp; bsrc = bqp; ldwS = 144; colS = d - 576; }
    else if (d < 864)  { wsrc = Wkp; bsrc = bkp; ldwS = 144; colS = d - 720; }
    else               { wsrc = Wvp; bsrc = bvp; ldwS = 288; colS = d - 864; }

    ull acc2[2][2];
    acc2[0][0] = acc2[0][1] = acc2[1][0] = acc2[1][1] = 0ull;

    for (int kk = 0; kk < CSV; kk += 16) {
        __syncthreads();
        if (t < 128) {
            float4 av = *(const float4*)&s[(size_t)(i0 + ar) * CSV + kk + ak];
            sA[ak + 0][ar] = av.x;
            sA[ak + 1][ar] = av.y;
            sA[ak + 2][ar] = av.z;
            sA[ak + 3][ar] = av.w;
        }
        float4 bv4 = *(const float4*)&wsrc[(size_t)(kk + bk2) * ldwS + colS];
        *(float4*)&sB[bk2][bn] = bv4;
        __syncthreads();
#pragma unroll
        for (int k = 0; k < 16; k++) {
            float2 a = *(const float2*)&sA[k][tr * 2];
            ulonglong2 b2 = *(const ulonglong2*)&sB[k][tc * 4];
            ull a0 = pack2(a.x, a.x);
            ull a1 = pack2(a.y, a.y);
            acc2[0][0] = ffma2(a0, b2.x, acc2[0][0]);
            acc2[0][1] = ffma2(a0, b2.y, acc2[0][1]);
            acc2[1][0] = ffma2(a1, b2.x, acc2[1][0]);
            acc2[1][1] = ffma2(a1, b2.y, acc2[1][1]);
        }
    }

    float4 bb4 = *(const float4*)&bsrc[colS];
#pragma unroll
    for (int i = 0; i < 2; i++) {
        float2 lo = unpack2(acc2[i][0]);
        float2 hi = unpack2(acc2[i][1]);
        float* crow = &g_raw[(size_t)(i0 + tr * 2 + i) * DPROJ + o0 + tc * 4];
        *(float4*)crow = make_float4(lo.x + bb4.x, lo.y + bb4.y,
                                     hi.x + bb4.z, hi.y + bb4.w);
    }
}

// ---------- register-tiled GEMM: 64x64 tile, 4x4 per thread (final) ----------
__global__ void gemm64_kernel(const float* __restrict__ A, int lda,
                              const float* __restrict__ W, int ldw,
                              float* __restrict__ C, int ldc, int kLen)
{
    __shared__ float sA[16][68];
    __shared__ float sB[16][68];
    int i0 = blockIdx.x * 64;
    int o0 = blockIdx.y * 64;
    int k0 = blockIdx.z * kLen;
    C += (size_t)blockIdx.z * (size_t)(gridDim.x * 64) * ldc;

    int t  = threadIdx.x;
    int tc = t & 15;
    int tr = t >> 4;

    int ar = t >> 2;
    int ak = (t & 3) * 4;
    int bk = t >> 4;
    int bn = (t & 15) * 4;

    ull acc2[4][2];
#pragma unroll
    for (int i = 0; i < 4; i++) { acc2[i][0] = 0ull; acc2[i][1] = 0ull; }

    for (int kk = 0; kk < kLen; kk += 16) {
        __syncthreads();
        float4 av = *(const float4*)&A[(size_t)(i0 + ar) * lda + k0 + kk + ak];
        sA[ak + 0][ar] = av.x;
        sA[ak + 1][ar] = av.y;
        sA[ak + 2][ar] = av.z;
        sA[ak + 3][ar] = av.w;
        float4 bv = *(const float4*)&W[(size_t)(k0 + kk + bk) * ldw + o0 + bn];
        *(float4*)&sB[bk][bn] = bv;
        __syncthreads();
#pragma unroll
        for (int k = 0; k < 16; k++) {
            float4 a = *(const float4*)&sA[k][tr * 4];
            ulonglong2 b2 = *(const ulonglong2*)&sB[k][tc * 4];
            ull a0 = pack2(a.x, a.x);
            ull a1 = pack2(a.y, a.y);
            ull a2 = pack2(a.z, a.z);
            ull a3 = pack2(a.w, a.w);
            acc2[0][0] = ffma2(a0, b2.x, acc2[0][0]);
            acc2[0][1] = ffma2(a0, b2.y, acc2[0][1]);
            acc2[1][0] = ffma2(a1, b2.x, acc2[1][0]);
            acc2[1][1] = ffma2(a1, b2.y, acc2[1][1]);
            acc2[2][0] = ffma2(a2, b2.x, acc2[2][0]);
            acc2[2][1] = ffma2(a2, b2.y, acc2[2][1]);
            acc2[3][0] = ffma2(a3, b2.x, acc2[3][0]);
            acc2[3][1] = ffma2(a3, b2.y, acc2[3][1]);
        }
    }

#pragma unroll
    for (int i = 0; i < 4; i++) {
        float2 lo = unpack2(acc2[i][0]);
        float2 hi = unpack2(acc2[i][1]);
        float* crow = &C[(size_t)(i0 + tr * 4 + i) * ldc + o0 + tc * 4];
        *(float4*)crow = make_float4(lo.x, lo.y, hi.x, hi.y);
    }
}

// ---------------- split-K reduce + bias (float4) -----------------------------
__global__ void reduce_kernel(const float* __restrict__ bias,
                              float* __restrict__ out)
{
    int idx = blockIdx.x * blockDim.x + threadIdx.x;
    if (idx >= NROWS / 4) return;
    const float4* p = (const float4*)g_part;
    float4 acc = p[idx];
#pragma unroll
    for (int k = 1; k < SPLITK; k++) {
        float4 v = p[idx + (size_t)k * (NROWS / 4)];
        acc.x += v.x; acc.y += v.y; acc.z += v.z; acc.w += v.w;
    }
    int col = (idx % (N_RESV / 4)) * 4;
    float4 bv = *(const float4*)&bias[col];
    acc.x += bv.x; acc.y += bv.y; acc.z += bv.z; acc.w += bv.w;
    ((float4*)out)[idx] = acc;
}

// ---------------- kernel 3: scatter projections + transform points -----------
__global__ void scatter_kernel(const float* __restrict__ T)
{
    int i = blockIdx.x;
    const float* raw = g_raw + (size_t)i * DPROJ;
    const float* Ti  = T + (size_t)i * 16;

    for (int t = threadIdx.x; t < 768; t += blockDim.x) {
        if (t < 576) {
            int kind = t / 192, d = t % 192;
            int h = d / 16, c = d % 16;
            float v = raw[kind * 192 + d];
            if (kind == 0) v *= 0.25f;
            float* dst = (kind == 0) ? g_q : ((kind == 1) ? g_k : g_v);
            dst[(h * N_RESV + i) * CHV + c] = v;
        } else {
            int t2 = t - 576;
            int kind, hp, P, base;
            if      (t2 < 48)  { kind = 0; hp = t2;       P = NQPV; base = 576; }
            else if (t2 < 96)  { kind = 1; hp = t2 - 48;  P = NQPV; base = 720; }
            else               { kind = 2; hp = t2 - 96;  P = NPVV; base = 864; }
            int HP = NHV * P;
            float px = raw[base + 0 * HP + hp];
            float py = raw[base + 1 * HP + hp];
            float pz = raw[base + 2 * HP + hp];
            float ox = Ti[0] * px + Ti[1] * py + Ti[2]  * pz + Ti[3];
            float oy = Ti[4] * px + Ti[5] * py + Ti[6]  * pz + Ti[7];
            float oz = Ti[8] * px + Ti[9] * py + Ti[10] * pz + Ti[11];
            float* dst = (kind == 0) ? g_tqp : ((kind == 1) ? g_tkp : g_tvp);
            float* o = dst + ((size_t)hp * N_RESV + i) * 3;
            o[0] = ox; o[1] = oy; o[2] = oz;
        }
    }
}

// ---------------- kernel 4: bias = z @ Wb + bb (16B cp.async, XOR swizzle) ---
// grid 1152, block 128; 128 rows/block, 1 row/thread, 12 heads, one z pass.
// sz rows are 128B; quad q of row r stored at physical quad (q ^ (r&7)).
__global__ void __launch_bounds__(128) bias_gemm_kernel(
    const float* __restrict__ z,
    const float* __restrict__ Wb,
    const float* __restrict__ bb)
{
    __shared__ __align__(16) float sz[2][128 * 32];   // 16 KB per buffer
    __shared__ __align__(16) ull   swp[NHV * 64];
    int t = threadIdx.x;
    int r0 = blockIdx.x * 128;

    unsigned sbase0 = smem_u32(&sz[0][0]);
    unsigned sbase1 = smem_u32(&sz[1][0]);

    for (int idx = t; idx < NHV * 64; idx += 128) {
        int h = idx >> 6, q = idx & 63;
        swp[idx] = pack2(Wb[(2 * q) * NHV + h], Wb[(2 * q + 1) * NHV + h]);
    }

    // prologue: issue chunks 0 and 1 (16B cp.async, swizzled dst)
#pragma unroll
    for (int c0 = 0; c0 < 2; c0++) {
        unsigned sb = c0 ? sbase1 : sbase0;
        int ct = c0 * 32;
#pragma unroll
        for (int k = 0; k < 8; k++) {
            int idx = t + (k << 7);
            int row = idx >> 3, q = idx & 7;
            unsigned sa = sb + (unsigned)(row * 128 + ((q ^ (row & 7)) << 4));
            const float* g = &z[(size_t)(r0 + row) * CZV + ct + q * 4];
            asm volatile("cp.async.cg.shared.global [%0], [%1], 16;\n"
                         :: "r"(sa), "l"(g));
        }
        asm volatile("cp.async.commit_group;\n");
    }

    ull acc[NHV];
#pragma unroll
    for (int h = 0; h < NHV; h++) acc[h] = 0ull;

    int r7 = t & 7;
#pragma unroll
    for (int c = 0; c < 4; c++) {
        if (c < 3) asm volatile("cp.async.wait_group 1;\n" ::: "memory");
        else       asm volatile("cp.async.wait_group 0;\n" ::: "memory");
        __syncthreads();
        const char* rowbase = (const char*)&sz[c & 1][0] + t * 128;
        int cbase = c << 4;
#pragma unroll
        for (int q = 0; q < 8; q++) {
            ulonglong2 zp = *(const ulonglong2*)(rowbase + ((q ^ r7) << 4));
            // zp.x = channel pair 2q, zp.y = pair 2q+1 (within chunk)
#pragma unroll
            for (int h = 0; h < NHV; h++) {
                ulonglong2 wp = *(const ulonglong2*)&swp[(h << 6) + cbase + 2 * q];
                ull a = acc[h];
                a = ffma2(zp.x, wp.x, a);
                a = ffma2(zp.y, wp.y, a);
                acc[h] = a;
            }
        }
        if (c < 2) {
            __syncthreads();
            unsigned sb = (c & 1) ? sbase1 : sbase0;
            int ct = (c + 2) * 32;
#pragma unroll
            for (int k = 0; k < 8; k++) {
                int idx = t + (k << 7);
                int row = idx >> 3, q = idx & 7;
                unsigned sa = sb + (unsigned)(row * 128 + ((q ^ (row & 7)) << 4));
                const float* g = &z[(size_t)(r0 + row) * CZV + ct + q * 4];
                asm volatile("cp.async.cg.shared.global [%0], [%1], 16;\n"
                             :: "r"(sa), "l"(g));
            }
            asm volatile("cp.async.commit_group;\n");
        }
    }

    int row = r0 + t;
#pragma unroll
    for (int h = 0; h < NHV; h++) {
        float2 v = unpack2(acc[h]);
        g_bias[(size_t)h * NROWS + row] = v.x + v.y + bb[h];
    }
}

// ---------------- kernel 5: logits + softmax, K-in-registers -----------------
__global__ void __launch_bounds__(384) att_kernel(const float* __restrict__ head_weights)
{
    int h = blockIdx.y;
    int i0 = blockIdx.x * 16;
    __shared__ float sq  [16][16];
    __shared__ float sqp [16][12];
    __shared__ float slog[16][N_RESV];

    int t = threadIdx.x;

    for (int idx = t; idx < 448; idx += 384) {
        if (idx < 256) {
            int iw = idx >> 4, c = idx & 15;
            sq[iw][c] = g_q[(h * N_RESV + i0 + iw) * CHV + c];
        } else {
            int u2 = idx - 256, iw = u2 / 12, u = u2 % 12, p = u / 3, d = u % 3;
            sqp[iw][u] = g_tqp[((h * NQPV + p) * N_RESV + i0 + iw) * 3 + d];
        }
    }

    float hw = head_weights[h];
    float gamma = (hw > 20.f) ? hw : log1pf(expf(hw));
    const float wc = 0.23570226039551584f;
    const float wl = 0.57735026918962576f;
    float coef = gamma * wc * 0.5f;

    int j = t;
    const float4* kr = (const float4*)&g_k[(h * N_RESV + j) * CHV];
    float4 k0 = kr[0], k1 = kr[1], k2 = kr[2], k3 = kr[3];
    float kp[12];
#pragma unroll
    for (int p = 0; p < NQPV; p++) {
        const float* kps = &g_tkp[((h * NQPV + p) * N_RESV + j) * 3];
        kp[p * 3 + 0] = kps[0];
        kp[p * 3 + 1] = kps[1];
        kp[p * 3 + 2] = kps[2];
    }
    __syncthreads();

    const float* bcol = &g_bias[(size_t)h * NROWS + (size_t)i0 * N_RESV + j];
#pragma unroll 4
    for (int i = 0; i < 16; i++) {
        const float* q = sq[i];
        float qk = q[0]  * k0.x + q[1]  * k0.y + q[2]  * k0.z + q[3]  * k0.w
                 + q[4]  * k1.x + q[5]  * k1.y + q[6]  * k1.z + q[7]  * k1.w
                 + q[8]  * k2.x + q[9]  * k2.y + q[10] * k2.z + q[11] * k2.w
                 + q[12] * k3.x + q[13] * k3.y + q[14] * k3.z + q[15] * k3.w;
        float d2 = 0.f;
#pragma unroll
        for (int p = 0; p < NQPV; p++) {
            float dx = sqp[i][p * 3 + 0] - kp[p * 3 + 0];
            float dy = sqp[i][p * 3 + 1] - kp[p * 3 + 1];
            float dz = sqp[i][p * 3 + 2] - kp[p * 3 + 2];
            d2 += dx * dx + dy * dy + dz * dz;
        }
        slog[i][j] = wl * (qk + bcol[(size_t)i * N_RESV] - coef * d2);
    }
    __syncthreads();

    int w = t >> 5, lane = t & 31;
    for (int rr = w; rr < 16; rr += 12) {
        float m = -1e30f;
#pragma unroll
        for (int r = 0; r < 12; r++) m = fmaxf(m, slog[rr][lane + r * 32]);
#pragma unroll
        for (int o = 16; o; o >>= 1) m = fmaxf(m, __shfl_xor_sync(0xffffffffu, m, o));
        float ss = 0.f;
#pragma unroll
        for (int r = 0; r < 12; r++) {
            float e = expf(slog[rr][lane + r * 32] - m);
            slog[rr][lane + r * 32] = e;
            ss += e;
        }
#pragma unroll
        for (int o = 16; o; o >>= 1) ss += __shfl_xor_sync(0xffffffffu, ss, o);
        float inv = 1.f / ss;
        float* arow = &g_att[(size_t)h * NROWS + (size_t)(i0 + rr) * N_RESV];
#pragma unroll
        for (int r = 0; r < 12; r++)
            arow[lane + r * 32] = slog[rr][lane + r * 32] * inv;
    }
}

// ---------------- kernel 6: per-head GEMM  att[h] @ [v|vp], f32x2 ------------
__global__ void att_av_kernel()
{
    int h = blockIdx.y;
    int i0 = blockIdx.x * 32;
    __shared__ float satt[32][65];
    __shared__ float sx[64][44];
    int t = threadIdx.x;
    int r  = t / 10;
    int c0 = (t % 10) * 4;
    ull acc2[2];
    acc2[0] = 0ull; acc2[1] = 0ull;

    for (int j0 = 0; j0 < N_RESV; j0 += 64) {
        __syncthreads();
        for (int idx = t; idx < 32 * 16; idx += 320) {
            int row = idx >> 4, v4 = idx & 15;
            float4 v = *(const float4*)&g_att[((size_t)h * N_RESV + i0 + row) * N_RESV + j0 + v4 * 4];
            float* dst = &satt[row][v4 * 4];
            dst[0] = v.x; dst[1] = v.y; dst[2] = v.z; dst[3] = v.w;
        }
        for (int idx = t; idx < 64 * 40; idx += 320) {
            int j = idx / 40, col = idx % 40;
            float v;
            if (col < 16) v = g_v[(h * N_RESV + j0 + j) * CHV + col];
            else {
                int u = col - 16, p = u / 3, d = u % 3;
                v = g_tvp[((h * NPVV + p) * N_RESV + j0 + j) * 3 + d];
            }
            sx[j][col] = v;
        }
        __syncthreads();
#pragma unroll 4
        for (int jj = 0; jj < 64; jj++) {
            float a = satt[r][jj];
            ull ap = pack2(a, a);
            ulonglong2 xr = *(const ulonglong2*)&sx[jj][c0];
            acc2[0] = ffma2(ap, xr.x, acc2[0]);
            acc2[1] = ffma2(ap, xr.y, acc2[1]);
        }
    }
    float2 lo = unpack2(acc2[0]);
    float2 hi = unpack2(acc2[1]);
    float* orow = &g_av[((size_t)h * N_RESV + i0 + r) * 40 + c0];
    *(float4*)orow = make_float4(lo.x, lo.y, hi.x, hi.y);
}

// ---------------- kernel 7: pairwise GEMM + finalize (cp.async z) ------------
#define ZROWS 16
__global__ void __launch_bounds__(384) out_kernel(const float* __restrict__ z,
                                                  const float* __restrict__ T)
{
    int i = blockIdx.x;
    __shared__ float att[NHV][N_RESV];
    __shared__ __align__(16) float zb[2][ZROWS][132];
    int t = threadIdx.x;

    unsigned zb0 = smem_u32(&zb[0][0][0]);
    unsigned zb1 = smem_u32(&zb[1][0][0]);
    const float* zsrc = z + (size_t)i * N_RESV * CZV;

#pragma unroll
    for (int c0 = 0; c0 < 2; c0++) {
        unsigned sb = c0 ? zb1 : zb0;
        for (int idx = t; idx < ZROWS * 32; idx += 384) {
            int row = idx >> 5, cq = idx & 31;
            unsigned sa = sb + (unsigned)(row * 132 + cq * 4) * 4u;
            const float* g = zsrc + (size_t)(c0 * ZROWS + row) * CZV + cq * 4;
            asm volatile("cp.async.cg.shared.global [%0], [%1], 16;\n"
                         :: "r"(sa), "l"(g));
        }
        asm volatile("cp.async.commit_group;\n");
    }

    for (int idx = t; idx < NHV * N_RESV / 4; idx += 384) {
        int h = idx / (N_RESV / 4), q = idx % (N_RESV / 4);
        float4 v = *(const float4*)&g_att[((size_t)h * N_RESV + i) * N_RESV + q * 4];
        *(float4*)&att[h][q * 4] = v;
    }

    int h  = t >> 5;
    int c4 = t & 31;
    const float* arow = att[h];

    ull acc01 = 0ull, acc23 = 0ull;
    const int NCHUNK = N_RESV / ZROWS;   // 24
    for (int c = 0; c < NCHUNK; c++) {
        if (c < NCHUNK - 1) asm volatile("cp.async.wait_group 1;\n" ::: "memory");
        else                asm volatile("cp.async.wait_group 0;\n" ::: "memory");
        __syncthreads();
        int b = c & 1;
        int j0 = c * ZROWS;
#pragma unroll
        for (int jj = 0; jj < ZROWS; jj++) {
            float a = arow[j0 + jj];
            ull ap = pack2(a, a);
            ulonglong2 zp = *(const ulonglong2*)&zb[b][jj][c4 * 4];
            acc01 = ffma2(ap, zp.x, acc01);
            acc23 = ffma2(ap, zp.y, acc23);
        }
        if (c < NCHUNK - 2) {
            __syncthreads();
            unsigned sb = (c & 1) ? zb1 : zb0;
            for (int idx = t; idx < ZROWS * 32; idx += 384) {
                int row = idx >> 5, cq = idx & 31;
                unsigned sa = sb + (unsigned)(row * 132 + cq * 4) * 4u;
                const float* g = zsrc + (size_t)((c + 2) * ZROWS + row) * CZV + cq * 4;
                asm volatile("cp.async.cg.shared.global [%0], [%1], 16;\n"
                             :: "r"(sa), "l"(g));
            }
            asm volatile("cp.async.commit_group;\n");
        }
    }
    float2 lo = unpack2(acc01);
    float2 hi = unpack2(acc23);
    float* crow = g_concat + (size_t)i * DCAT;
    *(float4*)&crow[576 + h * CZV + c4 * 4] = make_float4(lo.x, lo.y, hi.x, hi.y);

    if (t < 192) {
        int hh = t / 16, cc = t % 16;
        crow[hh * 16 + cc] = g_av[((size_t)hh * N_RESV + i) * 40 + cc];
    }
    const float* Ti = T + (size_t)i * 16;
    if (t < 96) {
        int hh = t / 8, p = t % 8;
        const float* av = &g_av[((size_t)hh * N_RESV + i) * 40 + 16 + p * 3];
        float px = av[0] - Ti[3];
        float py = av[1] - Ti[7];
        float pz = av[2] - Ti[11];
        float ox = Ti[0] * px + Ti[4] * py + Ti[8]  * pz;
        float oy = Ti[1] * px + Ti[5] * py + Ti[9]  * pz;
        float oz = Ti[2] * px + Ti[6] * py + Ti[10] * pz;
        crow[192 +   0 + hh * 8 + p] = ox;
        crow[192 +  96 + hh * 8 + p] = oy;
        crow[192 + 192 + hh * 8 + p] = oz;
        crow[480 + hh * 8 + p] = sqrtf(ox * ox + oy * oy + oz * oz);
    }
}

// ---------------- launch ------------------------------------------------------
extern "C" void kernel_launch(void* const* d_in, const int* in_sizes, int n_in,
                              void* d_out, int out_size)
{
    const float* s   = (const float*)d_in[0];
    const float* z   = (const float*)d_in[1];
    const float* T   = (const float*)d_in[2];
    const float* Wq  = (const float*)d_in[3];
    const float* bq  = (const float*)d_in[4];
    const float* Wk  = (const float*)d_in[5];
    const float* bk  = (const float*)d_in[6];
    const float* Wv  = (const float*)d_in[7];
    const float* bv  = (const float*)d_in[8];
    const float* Wqp = (const float*)d_in[9];
    const float* bqp = (const float*)d_in[10];
    const float* Wkp = (const float*)d_in[11];
    const float* bkp = (const float*)d_in[12];
    const float* Wvp = (const float*)d_in[13];
    const float* bvp = (const float*)d_in[14];
    const float* Wb  = (const float*)d_in[15];
    const float* bb  = (const float*)d_in[16];
    const float* Wo  = (const float*)d_in[17];
    const float* bo  = (const float*)d_in[18];
    const float* hwt = (const float*)d_in[19];

    float* out = (float*)d_out;

    float* concat_p; cudaGetSymbolAddress((void**)&concat_p, g_concat);
    float* part_p;   cudaGetSymbolAddress((void**)&part_p,   g_part);

    proj_gemm_kernel<<<dim3(N_RESV / 32, DPROJ / 64), 256>>>(
        s, Wq, bq, Wk, bk, Wv, bv, Wqp, bqp, Wkp, bkp, Wvp, bvp);

    scatter_kernel<<<N_RESV, 256>>>(T);

    bias_gemm_kernel<<<NROWS / 128, 128>>>(z, Wb, bb);

    att_kernel<<<dim3(24, NHV), 384>>>(hwt);

    att_av_kernel<<<dim3(12, NHV), 320>>>();

    out_kernel<<<N_RESV, 384>>>(z, T);

    gemm64_kernel<<<dim3(N_RESV / 64, N_RESV / 64, SPLITK), 256>>>(
        concat_p, DCAT, Wo, CSV, part_p, CSV, KSLICE);

    reduce_kernel<<<(NROWS / 4 + 255) / 256, 256>>>(bo, out);
}